// round 13
// baseline (speedup 1.0000x reference)
#include <cuda_runtime.h>
#include <cuda_fp16.h>
#include <math.h>
#include <stdint.h>

#define BB   16
#define TT   1500
#define DD   1024
#define DH   1023
#define DTXT 4096
#define NTOK 375
#define MM   (BB*NTOK)     // 6000
#define MAXP 12288
#define LDH  1024

// ---------------------------------------------------------------------------
// Device scratch
// ---------------------------------------------------------------------------
__device__ float g_numpred[BB];
__device__ int   g_nf[BB];
__device__ int   g_nt[BB];
__device__ int2  g_pairs[BB*MAXP];
__device__ int   g_rowptr[BB*(NTOK+1)];
__device__ int   g_rowmap[MM];                  // compact -> b*NTOK+n
__device__ int   g_Mp[1];                       // M' = sum(nt)
__device__ float g_h2 [(size_t)MM*DD];
__device__ __half g_ahi[(size_t)MM*LDH];
__device__ __half g_alo[(size_t)MM*LDH];
__device__ __half g_bhi[(size_t)DTXT*DD];
__device__ float g_embed[DD];                   // rmsnorm(cif_b)*ln_w
__device__ float g_outempty[DTXT];              // shared empty-row output

__device__ __forceinline__ void split_h(float x, __half& h, __half& l) {
    h = __float2half(x);
    l = __float2half(x - __half2float(h));
}

// ---------------------------------------------------------------------------
__global__ void k_detect(const void* nf_raw, const void* nt_raw) {
    const int* a = (const int*)nf_raw;
    const int* b = (const int*)nt_raw;
    bool is64 = (a[1] == 0) && (a[3] == 0) && (a[5] == 0);
    for (int i = 0; i < BB; i++) {
        if (is64) {
            g_nf[i] = (int)((const long long*)nf_raw)[i];
            g_nt[i] = (int)((const long long*)nt_raw)[i];
        } else {
            g_nf[i] = a[i];
            g_nt[i] = b[i];
        }
    }
}

// ---------------------------------------------------------------------------
// CIF v6: fused alphas + BRANCH-FREE exact scan (unconditional emission of
// <=2 pairs/frame incl. zero-weight pairs, statically addressed) + compact
// row map. Slow-path fallback unchanged (bit-exact reference semantics).
// ---------------------------------------------------------------------------
#define CIF_SMEM (BB*TT*4 + BB*(NTOK+1)*4)

__global__ void __launch_bounds__(512) k_cif6(const float* __restrict__ af) {
    extern __shared__ char cs[];
    float* sal   = (float*)cs;
    int*   slast = (int*)(cs + BB*TT*4);
    __shared__ int s_off[BB+1];
    int tid = threadIdx.x;
    int w = tid >> 5, lane = tid & 31;

    // phase A: warp w = batch w
    {
        int b = w;
        int nf = g_nf[b];
        float s = 0.f;
        for (int t = lane; t < TT; t += 32) {
            float x  = af[((size_t)b*TT + t)*DD + (DD-1)];
            float sg = 1.0f / (1.0f + expf(-x));
            if (t >= nf) sg = 0.f;
            sal[b*TT + t] = sg;
            s += sg;
        }
        #pragma unroll
        for (int o = 16; o > 0; o >>= 1)
            s += __shfl_xor_sync(0xFFFFFFFFu, s, o);
        if (lane == 0) g_numpred[b] = s;
        float scale = (float)g_nt[b] / s;
        for (int t = lane; t < TT; t += 32)
            sal[b*TT + t] *= scale;
    }
    if (tid == 0) {
        s_off[0] = 0;
        for (int b = 0; b < BB; b++) s_off[b+1] = s_off[b] + g_nt[b];
        g_Mp[0] = s_off[BB];
    }
    __syncthreads();
    {
        int b = w, o = s_off[b], n_t = g_nt[b];
        for (int n = lane; n < n_t; n += 32)
            g_rowmap[o + n] = b*NTOK + n;
    }
    for (int i = tid; i < BB*(NTOK+1); i += 512) slast[i] = 0;
    __syncthreads();

    // phase B: exact scan (warp 0, lanes 0..15), branch-free fast path
    if (tid < BB) {
        const unsigned FULL = 0xFFFFu;
        int b = tid;
        const float* al = sal + b*TT;
        int* lrow = slast + b*(NTOK+1);
        int base = b * MAXP;
        int nt1 = g_nt[b] - 1;

        float integrate = 0.f;
        int idx = 0;
        bool efire = false;

        float a = al[0];
        #pragma unroll 4
        for (int t = 0; t < TT-1; t++) {
            float a_next = al[t+1];
            float an = 1.f - integrate;
            integrate += a;
            bool ready = (integrate >= 1.f);
            float aint = ready ? an : a;
            if (ready) integrate -= 1.f;
            float w1 = a - aint;                 // 0 when not fired
            int n0 = idx;
            if (ready) idx = min(idx + 1, nt1);
            efire |= (integrate >= 1.f);
            // unconditional emission: slots 2t, 2t+1 (zero pairs are inert)
            g_pairs[base + 2*t]     = make_int2(t, __float_as_int(aint));
            g_pairs[base + 2*t + 1] = make_int2(t, __float_as_int(w1));
            lrow[n0]  = 2*t + 1;
            lrow[idx] = 2*t + 2;
            a = a_next;
        }
        // final frame TT-1: set-value only; remainder dropped (as reference)
        {
            int t = TT-1;
            float an = 1.f - integrate;
            integrate += a;
            bool ready = (integrate >= 1.f);
            float aint = ready ? an : a;
            if (ready) integrate -= 1.f;
            int n0 = idx;
            efire |= (integrate >= 1.f);
            g_pairs[base + 2*t] = make_int2(t, __float_as_int(aint));
            lrow[n0] = 2*t + 1;
        }

        // slow-path fallback (bit-exact reference semantics; never taken)
        bool slow = __any_sync(FULL, efire);
        if (slow) {
            for (int n = 0; n <= NTOK; n++) lrow[n] = 0;
            integrate = 0.f; idx = 0;
            int pcnt = 0;
            float prem = 0.f;
            int pn[6]; float pw[6]; int pc = 0;
            for (int t = 0; t < TT; t++) {
                if (t > 0) {
                    if (prem != 0.f) {
                        #pragma unroll
                        for (int j = 0; j < 6; j++)
                            if (j == pc) { pn[j] = idx; pw[j] = prem; }
                        if (pc < 6) pc++;
                    }
                    #pragma unroll
                    for (int i = 0; i < 6; i++) {
                        if (i < pc && pw[i] != 0.f && pcnt < MAXP) {
                            g_pairs[base+pcnt] = make_int2(t-1, __float_as_int(pw[i]));
                            lrow[pn[i]] = pcnt + 1; pcnt++;
                        }
                    }
                    pc = 0;
                }
                float av = al[t];
                float an = 1.f - integrate;
                integrate += av;
                bool ready = (integrate >= 1.f);
                if (ready) integrate -= 1.f;
                float aint = ready ? an : av;
                pn[0] = idx; pw[0] = aint; pc = 1;
                prem = av - aint;
                if (ready) idx = min(idx + 1, nt1);
                #pragma unroll
                for (int e = 0; e < 3; e++) {
                    bool any = __any_sync(FULL, integrate >= 1.f);
                    if (any) {
                        bool r2 = (integrate >= 1.f);
                        if (r2) integrate -= 1.f;
                        float ai2 = r2 ? 1.f : prem;
                        bool found = false;
                        #pragma unroll
                        for (int j = 0; j < 6; j++)
                            if (j < pc && pn[j] == idx && !found) { pw[j] = ai2; found = true; }
                        if (!found) {
                            #pragma unroll
                            for (int j = 0; j < 6; j++)
                                if (j == pc) { pn[j] = idx; pw[j] = ai2; }
                            if (pc < 6) pc++;
                        }
                        prem = prem - ai2;
                        if (r2) idx = min(idx + 1, nt1);
                    }
                }
            }
            #pragma unroll
            for (int i = 0; i < 6; i++) {
                if (i < pc && pw[i] != 0.f && pcnt < MAXP) {
                    g_pairs[base+pcnt] = make_int2(TT-1, __float_as_int(pw[i]));
                    lrow[pn[i]] = pcnt + 1; pcnt++;
                }
            }
        } else {
            __any_sync(FULL, false);
        }

        int* rp = &g_rowptr[b*(NTOK+1)];
        rp[0] = 0;
        int p = 0;
        for (int n = 0; n < NTOK; n++) {
            int v = lrow[n];
            if (v > 0) p = v;
            rp[n+1] = p;
        }
    }
}

// ---------------------------------------------------------------------------
// k_h1 (compact): skips zero-weight pairs (warp-uniform branch)
// ---------------------------------------------------------------------------
__global__ void k_h1(const float* __restrict__ af) {
    int r = blockIdx.x;
    if (r >= g_Mp[0]) return;
    int bn = g_rowmap[r];
    int b = bn / NTOK, n = bn % NTOK;
    int s = g_rowptr[b*(NTOK+1) + n];
    int e = g_rowptr[b*(NTOK+1) + n + 1];
    int d = threadIdx.x;
    float a0 = 0.f, a1 = 0.f, a2 = 0.f, a3 = 0.f;
    for (int p = s; p < e; p++) {
        int2 pr = g_pairs[b*MAXP + p];
        if (pr.y == 0) continue;                 // zero-weight pair: inert
        float w = __int_as_float(pr.y);
        const float* row = af + ((size_t)b*TT + pr.x)*DD;
        a0 += w * row[d];
        a1 += w * row[d + 256];
        a2 += w * row[d + 512];
        if (d + 768 < DH) a3 += w * row[d + 768];
    }
    size_t o = (size_t)r*LDH;
    __half h, l;
    split_h(a0, h, l); g_ahi[o+d]     = h; g_alo[o+d]     = l;
    split_h(a1, h, l); g_ahi[o+d+256] = h; g_alo[o+d+256] = l;
    split_h(a2, h, l); g_ahi[o+d+512] = h; g_alo[o+d+512] = l;
    if (d + 768 < DH) { split_h(a3, h, l); g_ahi[o+d+768] = h; g_alo[o+d+768] = l; }
    else { g_ahi[o+1023] = __float2half(0.f); g_alo[o+1023] = __float2half(0.f); }
}

// ---------------------------------------------------------------------------
__global__ void k_padw_hi(const float* __restrict__ w) {
    int i = blockIdx.x * 256 + threadIdx.x;
    int n = i >> 10, k = i & 1023;
    float v = (k < DH) ? w[(size_t)n*DH + k] : 0.f;
    g_bhi[i] = __float2half(v);
}
__global__ void k_w_hi(const float* __restrict__ w) {
    int i = blockIdx.x * 256 + threadIdx.x;
    g_bhi[i] = __float2half(w[i]);
}

// ---------------------------------------------------------------------------
__global__ void k_rms(const float* __restrict__ lnw) {
    int r = blockIdx.x;
    if (r >= g_Mp[0]) return;
    const float* hp = g_h2 + (size_t)r*DD;
    int tid = threadIdx.x;
    float v0 = hp[tid], v1 = hp[tid+256], v2 = hp[tid+512], v3 = hp[tid+768];
    __shared__ float red[256];
    red[tid] = v0*v0 + v1*v1 + v2*v2 + v3*v3;
    __syncthreads();
    for (int o = 128; o > 0; o >>= 1) {
        if (tid < o) red[tid] += red[tid + o];
        __syncthreads();
    }
    float inv = rsqrtf(red[0] * (1.0f/DD) + 1e-6f);
    size_t o = (size_t)r*DD;
    g_ahi[o+tid]     = __float2half(v0*inv*lnw[tid]);
    g_ahi[o+tid+256] = __float2half(v1*inv*lnw[tid+256]);
    g_ahi[o+tid+512] = __float2half(v2*inv*lnw[tid+512]);
    g_ahi[o+tid+768] = __float2half(v3*inv*lnw[tid+768]);
}

// ---------------------------------------------------------------------------
// Empty-row pipeline (fp32)
// ---------------------------------------------------------------------------
__global__ void k_empty1(const float* __restrict__ cb, const float* __restrict__ lnw) {
    int tid = threadIdx.x;
    float v0 = cb[tid], v1 = cb[tid+256], v2 = cb[tid+512], v3 = cb[tid+768];
    __shared__ float red[256];
    red[tid] = v0*v0 + v1*v1 + v2*v2 + v3*v3;
    __syncthreads();
    for (int o = 128; o > 0; o >>= 1) {
        if (tid < o) red[tid] += red[tid + o];
        __syncthreads();
    }
    float inv = rsqrtf(red[0] * (1.0f/DD) + 1e-6f);
    g_embed[tid]     = v0 * inv * lnw[tid];
    g_embed[tid+256] = v1 * inv * lnw[tid+256];
    g_embed[tid+512] = v2 * inv * lnw[tid+512];
    g_embed[tid+768] = v3 * inv * lnw[tid+768];
}
__global__ void k_empty2(const float* __restrict__ tw, const float* __restrict__ tb) {
    int c = blockIdx.x;
    int tid = threadIdx.x;
    const float* wr = tw + (size_t)c*DD;
    float s = 0.f;
    #pragma unroll
    for (int i = 0; i < 4; i++)
        s += g_embed[tid + i*256] * wr[tid + i*256];
    __shared__ float red[256];
    red[tid] = s;
    __syncthreads();
    for (int o = 128; o > 0; o >>= 1) {
        if (tid < o) red[tid] += red[tid + o];
        __syncthreads();
    }
    if (tid == 0) g_outempty[c] = red[0] + tb[c];
}
__global__ void k_fill(float* __restrict__ out) {
    int r = blockIdx.x;
    int b = r / NTOK, n = r % NTOK;
    if (n < g_nt[b]) return;
    float4* dst = (float4*)(out + (size_t)r*DTXT);
    const float4* src = (const float4*)g_outempty;
    for (int i = threadIdx.x; i < DTXT/4; i += 256)
        dst[i] = src[i];
}

// ---------------------------------------------------------------------------
// fp16 tensor-core GEMM (128x128, warp 64x32, BK=32) — at HMMA ceiling.
// ---------------------------------------------------------------------------
#define AROWB     80
#define ATILEB    (128*AROWB)

__device__ __forceinline__ void cp16(uint32_t dst, const void* src) {
    asm volatile("cp.async.cg.shared.global [%0], [%1], 16;"
                 :: "r"(dst), "l"(src) : "memory");
}
__device__ __forceinline__ void ldsm4(uint32_t r[4], uint32_t addr) {
    asm volatile("ldmatrix.sync.aligned.m8n8.x4.shared.b16 {%0,%1,%2,%3}, [%4];"
                 : "=r"(r[0]), "=r"(r[1]), "=r"(r[2]), "=r"(r[3]) : "r"(addr));
}
__device__ __forceinline__ void mma_h(float d[4], const uint32_t a[4],
                                      uint32_t b0, uint32_t b1) {
    asm volatile(
        "mma.sync.aligned.m16n8k16.row.col.f32.f16.f16.f32 "
        "{%0,%1,%2,%3}, {%4,%5,%6,%7}, {%8,%9}, {%0,%1,%2,%3};"
        : "+f"(d[0]), "+f"(d[1]), "+f"(d[2]), "+f"(d[3])
        : "r"(a[0]), "r"(a[1]), "r"(a[2]), "r"(a[3]), "r"(b0), "r"(b1));
}

template<int NPASS, bool SCATTER>
__global__ void __launch_bounds__(256)
gemm_h(int K,
       const __half* __restrict__ Ah, const __half* __restrict__ Al, int lda,
       const __half* __restrict__ Bh, int ldb,
       const float* __restrict__ bias,
       float* __restrict__ C, int ldc)
{
    constexpr int NA = (NPASS == 2) ? 2 : 1;
    constexpr uint32_t STAGEB = (NA + 1) * ATILEB;
    extern __shared__ __align__(128) char smem[];
    uint32_t sbase = (uint32_t)__cvta_generic_to_shared(smem);

    int M = g_Mp[0];
    int m0 = blockIdx.y * 128;
    if (m0 >= M) return;
    int tid  = threadIdx.x;
    int wid  = tid >> 5, lane = tid & 31;
    int g    = lane >> 2, tig = lane & 3;
    int n0   = blockIdx.x * 128;
    int wm   = (wid & 1) * 64;
    int wn   = (wid >> 1) * 32;

    float acc[4][4][4];
    #pragma unroll
    for (int i = 0; i < 4; i++)
        #pragma unroll
        for (int j = 0; j < 4; j++)
            #pragma unroll
            for (int q = 0; q < 4; q++) acc[i][j][q] = 0.f;

    const int nt = K >> 5;

    auto load_stage = [&](int s, int kt) {
        uint32_t st = sbase + (uint32_t)s * STAGEB;
        int k0 = kt << 5;
        #pragma unroll
        for (int c = tid; c < 512; c += 256) {
            int row = c >> 2, ch = (c & 3) << 4;
            int ke = k0 + (ch >> 1);
            int gm = m0 + row; if (gm >= M) gm = M - 1;
            uint32_t d = st + row*AROWB + ch;
            cp16(d, Ah + (size_t)gm*lda + ke);
            if (NPASS == 2) cp16(d + ATILEB, Al + (size_t)gm*lda + ke);
            cp16(st + NA*ATILEB + row*AROWB + ch, Bh + (size_t)(n0 + row)*ldb + ke);
        }
        asm volatile("cp.async.commit_group;" ::: "memory");
    };

    load_stage(0, 0);

    int quad = lane >> 3, qr = lane & 7;
    for (int kt = 0; kt < nt; kt++) {
        int buf = kt & 1;
        if (kt + 1 < nt) {
            load_stage(buf ^ 1, kt + 1);
            asm volatile("cp.async.wait_group 1;" ::: "memory");
        } else {
            asm volatile("cp.async.wait_group 0;" ::: "memory");
        }
        __syncthreads();

        uint32_t st = sbase + (uint32_t)buf * STAGEB;
        #pragma unroll
        for (int ks = 0; ks < 2; ks++) {
            int kc = ks * 16;
            uint32_t ka = (uint32_t)((kc + ((quad >> 1) << 3)) << 1);
            uint32_t arow = st + (uint32_t)(wm + ((quad & 1) << 3) + qr) * AROWB + ka;
            uint32_t brow = st + NA*ATILEB
                          + (uint32_t)(wn + ((quad & 1) << 3) + qr) * AROWB + ka;

            uint32_t ah[4][4], al[4][4], bh[2][4];
            #pragma unroll
            for (int mi = 0; mi < 4; mi++) {
                ldsm4(ah[mi], arow + mi*16*AROWB);
                if (NPASS == 2) ldsm4(al[mi], arow + ATILEB + mi*16*AROWB);
            }
            #pragma unroll
            for (int nb = 0; nb < 2; nb++)
                ldsm4(bh[nb], brow + nb*16*AROWB);

            #pragma unroll
            for (int mi = 0; mi < 4; mi++)
                #pragma unroll
                for (int ni = 0; ni < 4; ni++) {
                    int nb = ni >> 1, sel = ni & 1;
                    mma_h(acc[mi][ni], ah[mi], bh[nb][sel], bh[nb][sel+2]);
                    if (NPASS == 2)
                        mma_h(acc[mi][ni], al[mi], bh[nb][sel], bh[nb][sel+2]);
                }
        }
        __syncthreads();
    }

    #pragma unroll
    for (int mi = 0; mi < 4; mi++) {
        int row0 = m0 + wm + mi*16 + g;
        int row1 = row0 + 8;
        int o0 = (SCATTER && row0 < M) ? g_rowmap[row0] : row0;
        int o1 = (SCATTER && row1 < M) ? g_rowmap[row1] : row1;
        #pragma unroll
        for (int ni = 0; ni < 4; ni++) {
            int col = n0 + wn + ni*8 + 2*tig;
            float b0 = bias[col], b1 = bias[col+1];
            if (row0 < M) {
                float2 v = { acc[mi][ni][0] + b0, acc[mi][ni][1] + b1 };
                *reinterpret_cast<float2*>(C + (size_t)o0*ldc + col) = v;
            }
            if (row1 < M) {
                float2 v = { acc[mi][ni][2] + b0, acc[mi][ni][3] + b1 };
                *reinterpret_cast<float2*>(C + (size_t)o1*ldc + col) = v;
            }
        }
    }
}

// ---------------------------------------------------------------------------
__global__ void k_tail(float* __restrict__ out, int out_size) {
    int i = threadIdx.x;
    if (i < BB && out_size >= MM*DTXT + 2*BB) {
        out[MM*DTXT + i]      = (float)g_nt[i];
        out[MM*DTXT + BB + i] = g_numpred[i];
    }
}

// ---------------------------------------------------------------------------
extern "C" void kernel_launch(void* const* d_in, const int* in_sizes, int n_in,
                              void* d_out, int out_size) {
    const float* af     = (const float*)d_in[0];
    const float* cif_w  = (const float*)d_in[1];
    const float* cif_b  = (const float*)d_in[2];
    const float* ln_w   = (const float*)d_in[3];
    const float* text_w = (const float*)d_in[4];
    const float* text_b = (const float*)d_in[5];
    const void*  nf     = d_in[6];
    const void*  nt     = d_in[7];
    float* out = (float*)d_out;

    void *p_h2=0, *p_ahi=0, *p_alo=0, *p_bhi=0;
    cudaGetSymbolAddress(&p_h2,  g_h2);
    cudaGetSymbolAddress(&p_ahi, g_ahi);
    cudaGetSymbolAddress(&p_alo, g_alo);
    cudaGetSymbolAddress(&p_bhi, g_bhi);

    const int SMEM2 = 2 * 3 * ATILEB;   // 61440
    const int SMEM1 = 2 * 2 * ATILEB;   // 40960
    cudaFuncSetAttribute((const void*)gemm_h<2,false>, cudaFuncAttributeMaxDynamicSharedMemorySize, SMEM2);
    cudaFuncSetAttribute((const void*)gemm_h<1,true>,  cudaFuncAttributeMaxDynamicSharedMemorySize, SMEM1);
    cudaFuncSetAttribute((const void*)k_cif6,          cudaFuncAttributeMaxDynamicSharedMemorySize, CIF_SMEM);

    k_detect<<<1, 1>>>(nf, nt);
    k_empty1<<<1, 256>>>(cif_b, ln_w);
    k_empty2<<<DTXT, 256>>>(text_w, text_b);
    k_cif6<<<1, 512, CIF_SMEM>>>(af);
    k_fill<<<MM, 256>>>(out);
    k_h1<<<MM, 256>>>(af);
    k_padw_hi<<<(DD*DD)/256, 256>>>(cif_w);

    // cif_proj (compact): 2-pass
    {
        dim3 grid(DD/128, (MM + 127)/128);
        gemm_h<2,false><<<grid, 256, SMEM2>>>(1024,
            (const __half*)p_ahi, (const __half*)p_alo, LDH,
            (const __half*)p_bhi, 1024,
            cif_b, (float*)p_h2, DD);
    }
    k_rms<<<MM, 256>>>(ln_w);
    k_w_hi<<<(DTXT*DD)/256, 256>>>(text_w);

    // text_proj (compact, scatter epilogue): 1-pass
    {
        dim3 grid(DTXT/128, (MM + 127)/128);
        gemm_h<1,true><<<grid, 256, SMEM1>>>(1024,
            (const __half*)p_ahi, (const __half*)p_alo, LDH,
            (const __half*)p_bhi, DD,
            text_b, out, DTXT);
    }
    k_tail<<<1, 32>>>(out, out_size);
}

// round 14
// speedup vs baseline: 1.1614x; 1.1614x over previous
#include <cuda_runtime.h>
#include <cuda_fp16.h>
#include <math.h>
#include <stdint.h>

#define BB   16
#define TT   1500
#define DD   1024
#define DH   1023
#define DTXT 4096
#define NTOK 375
#define MM   (BB*NTOK)     // 6000
#define MAXP 12288
#define LDH  1024

// ---------------------------------------------------------------------------
// Device scratch
// ---------------------------------------------------------------------------
__device__ float g_numpred[BB];
__device__ int   g_nf[BB];
__device__ int   g_nt[BB];
__device__ int2  g_pairs[BB*MAXP];
__device__ int   g_rowptr[BB*(NTOK+1)];
__device__ int   g_rowmap[MM];                  // compact -> b*NTOK+n
__device__ int   g_Mp[1];                       // M' = sum(nt)
__device__ float g_h2 [(size_t)MM*DD];
__device__ __half g_ahi[(size_t)MM*LDH];
__device__ __half g_alo[(size_t)MM*LDH];
__device__ __half g_bhi[(size_t)DTXT*DD];
__device__ float g_embed[DD];
__device__ float g_outempty[DTXT];

__device__ __forceinline__ void split_h(float x, __half& h, __half& l) {
    h = __float2half(x);
    l = __float2half(x - __half2float(h));
}

// ---------------------------------------------------------------------------
__global__ void k_detect(const void* nf_raw, const void* nt_raw) {
    const int* a = (const int*)nf_raw;
    const int* b = (const int*)nt_raw;
    bool is64 = (a[1] == 0) && (a[3] == 0) && (a[5] == 0);
    for (int i = 0; i < BB; i++) {
        if (is64) {
            g_nf[i] = (int)((const long long*)nf_raw)[i];
            g_nt[i] = (int)((const long long*)nt_raw)[i];
        } else {
            g_nf[i] = a[i];
            g_nt[i] = b[i];
        }
    }
}

// ---------------------------------------------------------------------------
// CIF v7: fused alphas + 2-phase exact scan:
//   pass 1 (serial, minimal chain) stores per-frame integrate values
//   pass 2 (parallel over frames) re-derives weights bit-exactly, emits
//   static-slot pairs, records fire frames; rowptr computed from fire
//   frames with range end clamped to 2*min(nf,TT-1)+1 (alphas==0 beyond).
// Slow-path fallback (reference semantics with votes) kept verbatim.
// smem: sal[BB*TT] | sinteg[BB*TT] | sff/lrow[BB*(NTOK+1)]
// ---------------------------------------------------------------------------
#define CIF_SMEM (BB*TT*4 + BB*TT*4 + BB*(NTOK+1)*4)   // 216064 B

__global__ void __launch_bounds__(512) k_cif7(const float* __restrict__ af) {
    extern __shared__ char cs[];
    float* sal    = (float*)cs;                       // [BB*TT]
    float* sinteg = (float*)(cs + BB*TT*4);           // [BB*TT]
    int*   sffall = (int*)(cs + 2*BB*TT*4);           // [BB*(NTOK+1)]
    __shared__ int s_off[BB+1];
    __shared__ int s_slow;
    int tid = threadIdx.x;
    int w = tid >> 5, lane = tid & 31;

    // ---- phase A: warp w = batch w (sigmoid, mask, sum, scale) ----
    {
        int b = w;
        int nf = g_nf[b];
        float s = 0.f;
        for (int t = lane; t < TT; t += 32) {
            float x  = af[((size_t)b*TT + t)*DD + (DD-1)];
            float sg = 1.0f / (1.0f + expf(-x));
            if (t >= nf) sg = 0.f;
            sal[b*TT + t] = sg;
            s += sg;
        }
        #pragma unroll
        for (int o = 16; o > 0; o >>= 1)
            s += __shfl_xor_sync(0xFFFFFFFFu, s, o);
        if (lane == 0) g_numpred[b] = s;
        float scale = (float)g_nt[b] / s;
        for (int t = lane; t < TT; t += 32)
            sal[b*TT + t] *= scale;
    }
    if (tid == 0) {
        s_off[0] = 0;
        for (int b = 0; b < BB; b++) s_off[b+1] = s_off[b] + g_nt[b];
        g_Mp[0] = s_off[BB];
        s_slow = 0;
    }
    __syncthreads();
    {
        int b = w, o = s_off[b], n_t = g_nt[b];
        for (int n = lane; n < n_t; n += 32)
            g_rowmap[o + n] = b*NTOK + n;
    }
    __syncthreads();

    // ---- pass 1: minimal serial scan (warp 0, lanes 0..15) ----
    if (tid < BB) {
        const unsigned FULL = 0xFFFFu;
        int b = tid;
        const float* al = sal + b*TT;
        float* ig = sinteg + b*TT;
        float integrate = 0.f;
        bool efire = false;
        #pragma unroll 4
        for (int t = 0; t < TT; t++) {
            float s = integrate + al[t];
            bool ready = (s >= 1.f);
            integrate = ready ? (s - 1.f) : s;
            ig[t] = integrate;
            efire |= (integrate >= 1.f);
        }
        bool slow = __any_sync(FULL, efire);
        if (tid == 0 && slow) s_slow = 1;
    }
    __syncthreads();

    if (!s_slow) {
        // ---- pass 2: parallel emission (warp w = batch w) ----
        int b = w;
        const float* al = sal + b*TT;
        const float* ig = sinteg + b*TT;
        int* sff = sffall + b*(NTOK+1);
        int base = b * MAXP;
        for (int n = lane; n <= NTOK; n += 32) sff[n] = 0x7FFFFFFF;
        __syncwarp();
        int kbase = 0;
        for (int t0 = 0; t0 < TT; t0 += 32) {
            int t = t0 + lane;
            bool valid = (t < TT);
            float a  = valid ? al[t] : 0.f;
            float ip = (valid && t > 0) ? ig[t-1] : 0.f;
            float s  = ip + a;
            bool ready = valid && (s >= 1.f);
            unsigned mask = __ballot_sync(0xFFFFFFFFu, ready);
            int k = kbase + __popc(mask & ((1u << lane) - 1u)) + 1;
            if (ready && k <= NTOK) sff[k] = t;
            float aint = ready ? (1.f - ip) : a;
            float w1 = a - aint;
            if (valid) {
                g_pairs[base + 2*t] = make_int2(t, __float_as_int(aint));
                if (t < TT-1)
                    g_pairs[base + 2*t + 1] = make_int2(t, __float_as_int(w1));
            }
            kbase += __popc(mask);
        }
        __syncwarp();
        // rowptr from fire frames
        int nt1 = g_nt[b] - 1;
        int nf  = g_nf[b];
        int end = 2 * min(nf, TT-1) + 1;
        int* rp = &g_rowptr[b*(NTOK+1)];
        for (int n = lane; n <= NTOK; n += 32) {
            int v;
            if (n == 0) v = 0;
            else if (n <= nt1) {
                int f = sff[n];
                v = (f == 0x7FFFFFFF) ? end : (2*f + 1);
            } else v = end;
            rp[n] = v;
        }
    } else if (tid < BB) {
        // ---- slow path: verified serial reference scan (never in practice)
        const unsigned FULL = 0xFFFFu;
        int b = tid;
        const float* al = sal + b*TT;
        int* lrow = sffall + b*(NTOK+1);
        int base = b * MAXP;
        int nt1 = g_nt[b] - 1;
        for (int n = 0; n <= NTOK; n++) lrow[n] = 0;
        float integrate = 0.f, prem = 0.f;
        int idx = 0, pcnt = 0;
        int pn[6]; float pw[6]; int pc = 0;
        for (int t = 0; t < TT; t++) {
            if (t > 0) {
                if (prem != 0.f) {
                    #pragma unroll
                    for (int j = 0; j < 6; j++)
                        if (j == pc) { pn[j] = idx; pw[j] = prem; }
                    if (pc < 6) pc++;
                }
                #pragma unroll
                for (int i = 0; i < 6; i++) {
                    if (i < pc && pw[i] != 0.f && pcnt < MAXP) {
                        g_pairs[base+pcnt] = make_int2(t-1, __float_as_int(pw[i]));
                        lrow[pn[i]] = pcnt + 1; pcnt++;
                    }
                }
                pc = 0;
            }
            float av = al[t];
            float an = 1.f - integrate;
            integrate += av;
            bool ready = (integrate >= 1.f);
            if (ready) integrate -= 1.f;
            float aint = ready ? an : av;
            pn[0] = idx; pw[0] = aint; pc = 1;
            prem = av - aint;
            if (ready) idx = min(idx + 1, nt1);
            #pragma unroll
            for (int e = 0; e < 3; e++) {
                bool any = __any_sync(FULL, integrate >= 1.f);
                if (any) {
                    bool r2 = (integrate >= 1.f);
                    if (r2) integrate -= 1.f;
                    float ai2 = r2 ? 1.f : prem;
                    bool found = false;
                    #pragma unroll
                    for (int j = 0; j < 6; j++)
                        if (j < pc && pn[j] == idx && !found) { pw[j] = ai2; found = true; }
                    if (!found) {
                        #pragma unroll
                        for (int j = 0; j < 6; j++)
                            if (j == pc) { pn[j] = idx; pw[j] = ai2; }
                        if (pc < 6) pc++;
                    }
                    prem = prem - ai2;
                    if (r2) idx = min(idx + 1, nt1);
                }
            }
        }
        #pragma unroll
        for (int i = 0; i < 6; i++) {
            if (i < pc && pw[i] != 0.f && pcnt < MAXP) {
                g_pairs[base+pcnt] = make_int2(TT-1, __float_as_int(pw[i]));
                lrow[pn[i]] = pcnt + 1; pcnt++;
            }
        }
        int* rp = &g_rowptr[b*(NTOK+1)];
        rp[0] = 0;
        int p = 0;
        for (int n = 0; n < NTOK; n++) {
            int v = lrow[n];
            if (v > 0) p = v;
            rp[n+1] = p;
        }
    }
}

// ---------------------------------------------------------------------------
// k_h1 (compact): zero-weight pairs skipped (inert)
// ---------------------------------------------------------------------------
__global__ void k_h1(const float* __restrict__ af) {
    int r = blockIdx.x;
    if (r >= g_Mp[0]) return;
    int bn = g_rowmap[r];
    int b = bn / NTOK, n = bn % NTOK;
    int s = g_rowptr[b*(NTOK+1) + n];
    int e = g_rowptr[b*(NTOK+1) + n + 1];
    int d = threadIdx.x;
    float a0 = 0.f, a1 = 0.f, a2 = 0.f, a3 = 0.f;
    for (int p = s; p < e; p++) {
        int2 pr = g_pairs[b*MAXP + p];
        if (pr.y == 0) continue;
        float w = __int_as_float(pr.y);
        const float* row = af + ((size_t)b*TT + pr.x)*DD;
        a0 += w * row[d];
        a1 += w * row[d + 256];
        a2 += w * row[d + 512];
        if (d + 768 < DH) a3 += w * row[d + 768];
    }
    size_t o = (size_t)r*LDH;
    __half h, l;
    split_h(a0, h, l); g_ahi[o+d]     = h; g_alo[o+d]     = l;
    split_h(a1, h, l); g_ahi[o+d+256] = h; g_alo[o+d+256] = l;
    split_h(a2, h, l); g_ahi[o+d+512] = h; g_alo[o+d+512] = l;
    if (d + 768 < DH) { split_h(a3, h, l); g_ahi[o+d+768] = h; g_alo[o+d+768] = l; }
    else { g_ahi[o+1023] = __float2half(0.f); g_alo[o+1023] = __float2half(0.f); }
}

// ---------------------------------------------------------------------------
__global__ void k_padw_hi(const float* __restrict__ w) {
    int i = blockIdx.x * 256 + threadIdx.x;
    int n = i >> 10, k = i & 1023;
    float v = (k < DH) ? w[(size_t)n*DH + k] : 0.f;
    g_bhi[i] = __float2half(v);
}
__global__ void k_w_hi(const float* __restrict__ w) {
    int i = blockIdx.x * 256 + threadIdx.x;
    g_bhi[i] = __float2half(w[i]);
}

// ---------------------------------------------------------------------------
__global__ void k_rms(const float* __restrict__ lnw) {
    int r = blockIdx.x;
    if (r >= g_Mp[0]) return;
    const float* hp = g_h2 + (size_t)r*DD;
    int tid = threadIdx.x;
    float v0 = hp[tid], v1 = hp[tid+256], v2 = hp[tid+512], v3 = hp[tid+768];
    __shared__ float red[256];
    red[tid] = v0*v0 + v1*v1 + v2*v2 + v3*v3;
    __syncthreads();
    for (int o = 128; o > 0; o >>= 1) {
        if (tid < o) red[tid] += red[tid + o];
        __syncthreads();
    }
    float inv = rsqrtf(red[0] * (1.0f/DD) + 1e-6f);
    size_t o = (size_t)r*DD;
    g_ahi[o+tid]     = __float2half(v0*inv*lnw[tid]);
    g_ahi[o+tid+256] = __float2half(v1*inv*lnw[tid+256]);
    g_ahi[o+tid+512] = __float2half(v2*inv*lnw[tid+512]);
    g_ahi[o+tid+768] = __float2half(v3*inv*lnw[tid+768]);
}

// ---------------------------------------------------------------------------
// Empty-row pipeline (fp32)
// ---------------------------------------------------------------------------
__global__ void k_empty1(const float* __restrict__ cb, const float* __restrict__ lnw) {
    int tid = threadIdx.x;
    float v0 = cb[tid], v1 = cb[tid+256], v2 = cb[tid+512], v3 = cb[tid+768];
    __shared__ float red[256];
    red[tid] = v0*v0 + v1*v1 + v2*v2 + v3*v3;
    __syncthreads();
    for (int o = 128; o > 0; o >>= 1) {
        if (tid < o) red[tid] += red[tid + o];
        __syncthreads();
    }
    float inv = rsqrtf(red[0] * (1.0f/DD) + 1e-6f);
    g_embed[tid]     = v0 * inv * lnw[tid];
    g_embed[tid+256] = v1 * inv * lnw[tid+256];
    g_embed[tid+512] = v2 * inv * lnw[tid+512];
    g_embed[tid+768] = v3 * inv * lnw[tid+768];
}
__global__ void k_empty2(const float* __restrict__ tw, const float* __restrict__ tb) {
    int c = blockIdx.x;
    int tid = threadIdx.x;
    const float* wr = tw + (size_t)c*DD;
    float s = 0.f;
    #pragma unroll
    for (int i = 0; i < 4; i++)
        s += g_embed[tid + i*256] * wr[tid + i*256];
    __shared__ float red[256];
    red[tid] = s;
    __syncthreads();
    for (int o = 128; o > 0; o >>= 1) {
        if (tid < o) red[tid] += red[tid + o];
        __syncthreads();
    }
    if (tid == 0) g_outempty[c] = red[0] + tb[c];
}
__global__ void k_fill(float* __restrict__ out) {
    int r = blockIdx.x;
    int b = r / NTOK, n = r % NTOK;
    if (n < g_nt[b]) return;
    float4* dst = (float4*)(out + (size_t)r*DTXT);
    const float4* src = (const float4*)g_outempty;
    for (int i = threadIdx.x; i < DTXT/4; i += 256)
        dst[i] = src[i];
}

// ---------------------------------------------------------------------------
// fp16 tensor-core GEMM (128x128, warp 64x32, BK=32) — at HMMA ceiling.
// ---------------------------------------------------------------------------
#define AROWB     80
#define ATILEB    (128*AROWB)

__device__ __forceinline__ void cp16(uint32_t dst, const void* src) {
    asm volatile("cp.async.cg.shared.global [%0], [%1], 16;"
                 :: "r"(dst), "l"(src) : "memory");
}
__device__ __forceinline__ void ldsm4(uint32_t r[4], uint32_t addr) {
    asm volatile("ldmatrix.sync.aligned.m8n8.x4.shared.b16 {%0,%1,%2,%3}, [%4];"
                 : "=r"(r[0]), "=r"(r[1]), "=r"(r[2]), "=r"(r[3]) : "r"(addr));
}
__device__ __forceinline__ void mma_h(float d[4], const uint32_t a[4],
                                      uint32_t b0, uint32_t b1) {
    asm volatile(
        "mma.sync.aligned.m16n8k16.row.col.f32.f16.f16.f32 "
        "{%0,%1,%2,%3}, {%4,%5,%6,%7}, {%8,%9}, {%0,%1,%2,%3};"
        : "+f"(d[0]), "+f"(d[1]), "+f"(d[2]), "+f"(d[3])
        : "r"(a[0]), "r"(a[1]), "r"(a[2]), "r"(a[3]), "r"(b0), "r"(b1));
}

template<int NPASS, bool SCATTER>
__global__ void __launch_bounds__(256)
gemm_h(int K,
       const __half* __restrict__ Ah, const __half* __restrict__ Al, int lda,
       const __half* __restrict__ Bh, int ldb,
       const float* __restrict__ bias,
       float* __restrict__ C, int ldc)
{
    constexpr int NA = (NPASS == 2) ? 2 : 1;
    constexpr uint32_t STAGEB = (NA + 1) * ATILEB;
    extern __shared__ __align__(128) char smem[];
    uint32_t sbase = (uint32_t)__cvta_generic_to_shared(smem);

    int M = g_Mp[0];
    int m0 = blockIdx.y * 128;
    if (m0 >= M) return;
    int tid  = threadIdx.x;
    int wid  = tid >> 5, lane = tid & 31;
    int g    = lane >> 2, tig = lane & 3;
    int n0   = blockIdx.x * 128;
    int wm   = (wid & 1) * 64;
    int wn   = (wid >> 1) * 32;

    float acc[4][4][4];
    #pragma unroll
    for (int i = 0; i < 4; i++)
        #pragma unroll
        for (int j = 0; j < 4; j++)
            #pragma unroll
            for (int q = 0; q < 4; q++) acc[i][j][q] = 0.f;

    const int nt = K >> 5;

    auto load_stage = [&](int s, int kt) {
        uint32_t st = sbase + (uint32_t)s * STAGEB;
        int k0 = kt << 5;
        #pragma unroll
        for (int c = tid; c < 512; c += 256) {
            int row = c >> 2, ch = (c & 3) << 4;
            int ke = k0 + (ch >> 1);
            int gm = m0 + row; if (gm >= M) gm = M - 1;
            uint32_t d = st + row*AROWB + ch;
            cp16(d, Ah + (size_t)gm*lda + ke);
            if (NPASS == 2) cp16(d + ATILEB, Al + (size_t)gm*lda + ke);
            cp16(st + NA*ATILEB + row*AROWB + ch, Bh + (size_t)(n0 + row)*ldb + ke);
        }
        asm volatile("cp.async.commit_group;" ::: "memory");
    };

    load_stage(0, 0);

    int quad = lane >> 3, qr = lane & 7;
    for (int kt = 0; kt < nt; kt++) {
        int buf = kt & 1;
        if (kt + 1 < nt) {
            load_stage(buf ^ 1, kt + 1);
            asm volatile("cp.async.wait_group 1;" ::: "memory");
        } else {
            asm volatile("cp.async.wait_group 0;" ::: "memory");
        }
        __syncthreads();

        uint32_t st = sbase + (uint32_t)buf * STAGEB;
        #pragma unroll
        for (int ks = 0; ks < 2; ks++) {
            int kc = ks * 16;
            uint32_t ka = (uint32_t)((kc + ((quad >> 1) << 3)) << 1);
            uint32_t arow = st + (uint32_t)(wm + ((quad & 1) << 3) + qr) * AROWB + ka;
            uint32_t brow = st + NA*ATILEB
                          + (uint32_t)(wn + ((quad & 1) << 3) + qr) * AROWB + ka;

            uint32_t ah[4][4], al[4][4], bh[2][4];
            #pragma unroll
            for (int mi = 0; mi < 4; mi++) {
                ldsm4(ah[mi], arow + mi*16*AROWB);
                if (NPASS == 2) ldsm4(al[mi], arow + ATILEB + mi*16*AROWB);
            }
            #pragma unroll
            for (int nb = 0; nb < 2; nb++)
                ldsm4(bh[nb], brow + nb*16*AROWB);

            #pragma unroll
            for (int mi = 0; mi < 4; mi++)
                #pragma unroll
                for (int ni = 0; ni < 4; ni++) {
                    int nb = ni >> 1, sel = ni & 1;
                    mma_h(acc[mi][ni], ah[mi], bh[nb][sel], bh[nb][sel+2]);
                    if (NPASS == 2)
                        mma_h(acc[mi][ni], al[mi], bh[nb][sel], bh[nb][sel+2]);
                }
        }
        __syncthreads();
    }

    #pragma unroll
    for (int mi = 0; mi < 4; mi++) {
        int row0 = m0 + wm + mi*16 + g;
        int row1 = row0 + 8;
        int o0 = (SCATTER && row0 < M) ? g_rowmap[row0] : row0;
        int o1 = (SCATTER && row1 < M) ? g_rowmap[row1] : row1;
        #pragma unroll
        for (int ni = 0; ni < 4; ni++) {
            int col = n0 + wn + ni*8 + 2*tig;
            float b0 = bias[col], b1 = bias[col+1];
            if (row0 < M) {
                float2 v = { acc[mi][ni][0] + b0, acc[mi][ni][1] + b1 };
                *reinterpret_cast<float2*>(C + (size_t)o0*ldc + col) = v;
            }
            if (row1 < M) {
                float2 v = { acc[mi][ni][2] + b0, acc[mi][ni][3] + b1 };
                *reinterpret_cast<float2*>(C + (size_t)o1*ldc + col) = v;
            }
        }
    }
}

// ---------------------------------------------------------------------------
__global__ void k_tail(float* __restrict__ out, int out_size) {
    int i = threadIdx.x;
    if (i < BB && out_size >= MM*DTXT + 2*BB) {
        out[MM*DTXT + i]      = (float)g_nt[i];
        out[MM*DTXT + BB + i] = g_numpred[i];
    }
}

// ---------------------------------------------------------------------------
extern "C" void kernel_launch(void* const* d_in, const int* in_sizes, int n_in,
                              void* d_out, int out_size) {
    const float* af     = (const float*)d_in[0];
    const float* cif_w  = (const float*)d_in[1];
    const float* cif_b  = (const float*)d_in[2];
    const float* ln_w   = (const float*)d_in[3];
    const float* text_w = (const float*)d_in[4];
    const float* text_b = (const float*)d_in[5];
    const void*  nf     = d_in[6];
    const void*  nt     = d_in[7];
    float* out = (float*)d_out;

    void *p_h2=0, *p_ahi=0, *p_alo=0, *p_bhi=0;
    cudaGetSymbolAddress(&p_h2,  g_h2);
    cudaGetSymbolAddress(&p_ahi, g_ahi);
    cudaGetSymbolAddress(&p_alo, g_alo);
    cudaGetSymbolAddress(&p_bhi, g_bhi);

    const int SMEM2 = 2 * 3 * ATILEB;   // 61440
    const int SMEM1 = 2 * 2 * ATILEB;   // 40960
    cudaFuncSetAttribute((const void*)gemm_h<2,false>, cudaFuncAttributeMaxDynamicSharedMemorySize, SMEM2);
    cudaFuncSetAttribute((const void*)gemm_h<1,true>,  cudaFuncAttributeMaxDynamicSharedMemorySize, SMEM1);
    cudaFuncSetAttribute((const void*)k_cif7,          cudaFuncAttributeMaxDynamicSharedMemorySize, CIF_SMEM);

    k_detect<<<1, 1>>>(nf, nt);
    k_empty1<<<1, 256>>>(cif_b, ln_w);
    k_empty2<<<DTXT, 256>>>(text_w, text_b);
    k_cif7<<<1, 512, CIF_SMEM>>>(af);
    k_fill<<<MM, 256>>>(out);
    k_h1<<<MM, 256>>>(af);
    k_padw_hi<<<(DD*DD)/256, 256>>>(cif_w);

    // cif_proj (compact): 2-pass
    {
        dim3 grid(DD/128, (MM + 127)/128);
        gemm_h<2,false><<<grid, 256, SMEM2>>>(1024,
            (const __half*)p_ahi, (const __half*)p_alo, LDH,
            (const __half*)p_bhi, 1024,
            cif_b, (float*)p_h2, DD);
    }
    k_rms<<<MM, 256>>>(ln_w);
    k_w_hi<<<(DTXT*DD)/256, 256>>>(text_w);

    // text_proj (compact, scatter epilogue): 1-pass
    {
        dim3 grid(DTXT/128, (MM + 127)/128);
        gemm_h<1,true><<<grid, 256, SMEM1>>>(1024,
            (const __half*)p_ahi, (const __half*)p_alo, LDH,
            (const __half*)p_bhi, DD,
            text_b, out, DTXT);
    }
    k_tail<<<1, 32>>>(out, out_size);
}

// round 15
// speedup vs baseline: 1.1821x; 1.0178x over previous
#include <cuda_runtime.h>
#include <cuda_fp16.h>
#include <math.h>
#include <stdint.h>

#define BB   16
#define TT   1500
#define DD   1024
#define DH   1023
#define DTXT 4096
#define NTOK 375
#define MM   (BB*NTOK)     // 6000
#define MAXP 12288
#define LDH  1024

// ---------------------------------------------------------------------------
// Device scratch
// ---------------------------------------------------------------------------
__device__ float g_numpred[BB];
__device__ int   g_nf[BB];
__device__ int   g_nt[BB];
__device__ int2  g_pairs[(size_t)MAXP*BB];      // INTERLEAVED: [slot*BB + b]
__device__ int   g_rowptr[BB*(NTOK+1)];
__device__ int   g_rowmap[MM];                  // compact -> b*NTOK+n
__device__ int   g_Mp[1];                       // M' = sum(nt)
__device__ float g_h2 [(size_t)MM*DD];
__device__ __half g_ahi[(size_t)MM*LDH];
__device__ __half g_alo[(size_t)MM*LDH];
__device__ __half g_bhi[(size_t)DTXT*DD];
__device__ float g_embed[DD];
__device__ float g_outempty[DTXT];

__device__ __forceinline__ void split_h(float x, __half& h, __half& l) {
    h = __float2half(x);
    l = __float2half(x - __half2float(h));
}

// ---------------------------------------------------------------------------
__global__ void k_detect(const void* nf_raw, const void* nt_raw) {
    const int* a = (const int*)nf_raw;
    const int* b = (const int*)nt_raw;
    bool is64 = (a[1] == 0) && (a[3] == 0) && (a[5] == 0);
    for (int i = 0; i < BB; i++) {
        if (is64) {
            g_nf[i] = (int)((const long long*)nf_raw)[i];
            g_nt[i] = (int)((const long long*)nt_raw)[i];
        } else {
            g_nf[i] = a[i];
            g_nt[i] = b[i];
        }
    }
}

// ---------------------------------------------------------------------------
// CIF v8: fused alphas + single-pass exact scan with COALESCED static-slot
// emission (interleaved pair layout) and computed rowptr from fire frames.
// Slow-path fallback (reference semantics, votes) kept; never taken.
// ---------------------------------------------------------------------------
#define CIF_SMEM (BB*TT*4 + BB*(NTOK+1)*4)   // 120064 B

__global__ void __launch_bounds__(512) k_cif8(const float* __restrict__ af) {
    extern __shared__ char cs[];
    float* sal    = (float*)cs;                       // [BB*TT]
    int*   sffall = (int*)(cs + BB*TT*4);             // [BB*(NTOK+1)]
    __shared__ int s_off[BB+1];
    int tid = threadIdx.x;
    int w = tid >> 5, lane = tid & 31;

    // ---- phase A: warp w = batch w (sigmoid, mask, sum, scale) ----
    {
        int b = w;
        int nf = g_nf[b];
        float s = 0.f;
        for (int t = lane; t < TT; t += 32) {
            float x  = af[((size_t)b*TT + t)*DD + (DD-1)];
            float sg = 1.0f / (1.0f + expf(-x));
            if (t >= nf) sg = 0.f;
            sal[b*TT + t] = sg;
            s += sg;
        }
        #pragma unroll
        for (int o = 16; o > 0; o >>= 1)
            s += __shfl_xor_sync(0xFFFFFFFFu, s, o);
        if (lane == 0) g_numpred[b] = s;
        float scale = (float)g_nt[b] / s;
        for (int t = lane; t < TT; t += 32)
            sal[b*TT + t] *= scale;
    }
    if (tid == 0) {
        s_off[0] = 0;
        for (int b = 0; b < BB; b++) s_off[b+1] = s_off[b] + g_nt[b];
        g_Mp[0] = s_off[BB];
    }
    __syncthreads();
    {
        int b = w, o = s_off[b], n_t = g_nt[b];
        for (int n = lane; n < n_t; n += 32)
            g_rowmap[o + n] = b*NTOK + n;
    }
    for (int i = tid; i < BB*(NTOK+1); i += 512) sffall[i] = 0x7FFFFFFF;
    __syncthreads();

    // ---- scan: warp 0, lanes 0..15 (one batch per lane) ----
    if (tid < BB) {
        const unsigned FULL = 0xFFFFu;
        int b = tid;
        const float* al = sal + b*TT;
        int* sff = sffall + b*(NTOK+1);

        float integrate = 0.f;
        int k = 0;
        bool efire = false;

        #pragma unroll 4
        for (int t = 0; t < TT; t++) {
            float a = al[t];
            float s = integrate + a;
            bool ready = (s >= 1.f);
            float aint = ready ? (1.f - integrate) : a;
            integrate = ready ? (s - 1.f) : s;
            float w1 = a - aint;
            k += ready ? 1 : 0;
            int sel = (ready && k < NTOK) ? k : NTOK;   // NTOK = dump slot
            sff[sel] = t;
            // coalesced static-slot emission (16 lanes -> one 128B line each)
            g_pairs[(size_t)(2*t)*BB + b]     = make_int2(t, __float_as_int(aint));
            g_pairs[(size_t)(2*t + 1)*BB + b] = make_int2(t, __float_as_int(w1));
            efire |= (integrate >= 1.f);
        }

        bool slow = __any_sync(FULL, efire);
        if (!slow) {
            // rowptr from fire frames; range end clamps inert tail
            int nt1 = g_nt[b] - 1;
            int nf  = g_nf[b];
            int end = 2 * min(nf, TT-1) + 1;
            int* rp = &g_rowptr[b*(NTOK+1)];
            rp[0] = 0;
            for (int n = 1; n <= NTOK; n++) {
                int v;
                if (n <= nt1) {
                    int f = sff[n];
                    v = (f == 0x7FFFFFFF) ? end : (2*f + 1);
                } else v = end;
                rp[n] = v;
            }
        } else {
            // ---- slow path: verified serial reference scan ----
            int* lrow = sff;
            for (int n = 0; n <= NTOK; n++) lrow[n] = 0;
            int nt1 = g_nt[b] - 1;
            integrate = 0.f;
            float prem = 0.f;
            int idx = 0, pcnt = 0;
            int pn[6]; float pw[6]; int pc = 0;
            for (int t = 0; t < TT; t++) {
                if (t > 0) {
                    if (prem != 0.f) {
                        #pragma unroll
                        for (int j = 0; j < 6; j++)
                            if (j == pc) { pn[j] = idx; pw[j] = prem; }
                        if (pc < 6) pc++;
                    }
                    #pragma unroll
                    for (int i = 0; i < 6; i++) {
                        if (i < pc && pw[i] != 0.f && pcnt < MAXP) {
                            g_pairs[(size_t)pcnt*BB + b] = make_int2(t-1, __float_as_int(pw[i]));
                            lrow[pn[i]] = pcnt + 1; pcnt++;
                        }
                    }
                    pc = 0;
                }
                float av = al[t];
                float an = 1.f - integrate;
                integrate += av;
                bool ready = (integrate >= 1.f);
                if (ready) integrate -= 1.f;
                float aint = ready ? an : av;
                pn[0] = idx; pw[0] = aint; pc = 1;
                prem = av - aint;
                if (ready) idx = min(idx + 1, nt1);
                #pragma unroll
                for (int e = 0; e < 3; e++) {
                    bool any = __any_sync(FULL, integrate >= 1.f);
                    if (any) {
                        bool r2 = (integrate >= 1.f);
                        if (r2) integrate -= 1.f;
                        float ai2 = r2 ? 1.f : prem;
                        bool found = false;
                        #pragma unroll
                        for (int j = 0; j < 6; j++)
                            if (j < pc && pn[j] == idx && !found) { pw[j] = ai2; found = true; }
                        if (!found) {
                            #pragma unroll
                            for (int j = 0; j < 6; j++)
                                if (j == pc) { pn[j] = idx; pw[j] = ai2; }
                            if (pc < 6) pc++;
                        }
                        prem = prem - ai2;
                        if (r2) idx = min(idx + 1, nt1);
                    }
                }
            }
            #pragma unroll
            for (int i = 0; i < 6; i++) {
                if (i < pc && pw[i] != 0.f && pcnt < MAXP) {
                    g_pairs[(size_t)pcnt*BB + b] = make_int2(TT-1, __float_as_int(pw[i]));
                    lrow[pn[i]] = pcnt + 1; pcnt++;
                }
            }
            int* rp = &g_rowptr[b*(NTOK+1)];
            rp[0] = 0;
            int p = 0;
            for (int n = 0; n < NTOK; n++) {
                int v = lrow[n];
                if (v > 0) p = v;
                rp[n+1] = p;
            }
        }
    }
}

// ---------------------------------------------------------------------------
// k_h1 (compact, interleaved pairs): zero-weight pairs skipped (inert)
// ---------------------------------------------------------------------------
__global__ void k_h1(const float* __restrict__ af) {
    int r = blockIdx.x;
    if (r >= g_Mp[0]) return;
    int bn = g_rowmap[r];
    int b = bn / NTOK, n = bn % NTOK;
    int s = g_rowptr[b*(NTOK+1) + n];
    int e = g_rowptr[b*(NTOK+1) + n + 1];
    int d = threadIdx.x;
    float a0 = 0.f, a1 = 0.f, a2 = 0.f, a3 = 0.f;
    for (int p = s; p < e; p++) {
        int2 pr = g_pairs[(size_t)p*BB + b];
        if (pr.y == 0) continue;
        float w = __int_as_float(pr.y);
        const float* row = af + ((size_t)b*TT + pr.x)*DD;
        a0 += w * row[d];
        a1 += w * row[d + 256];
        a2 += w * row[d + 512];
        if (d + 768 < DH) a3 += w * row[d + 768];
    }
    size_t o = (size_t)r*LDH;
    __half h, l;
    split_h(a0, h, l); g_ahi[o+d]     = h; g_alo[o+d]     = l;
    split_h(a1, h, l); g_ahi[o+d+256] = h; g_alo[o+d+256] = l;
    split_h(a2, h, l); g_ahi[o+d+512] = h; g_alo[o+d+512] = l;
    if (d + 768 < DH) { split_h(a3, h, l); g_ahi[o+d+768] = h; g_alo[o+d+768] = l; }
    else { g_ahi[o+1023] = __float2half(0.f); g_alo[o+1023] = __float2half(0.f); }
}

// ---------------------------------------------------------------------------
__global__ void k_padw_hi(const float* __restrict__ w) {
    int i = blockIdx.x * 256 + threadIdx.x;
    int n = i >> 10, k = i & 1023;
    float v = (k < DH) ? w[(size_t)n*DH + k] : 0.f;
    g_bhi[i] = __float2half(v);
}
__global__ void k_w_hi(const float* __restrict__ w) {
    int i = blockIdx.x * 256 + threadIdx.x;
    g_bhi[i] = __float2half(w[i]);
}

// ---------------------------------------------------------------------------
__global__ void k_rms(const float* __restrict__ lnw) {
    int r = blockIdx.x;
    if (r >= g_Mp[0]) return;
    const float* hp = g_h2 + (size_t)r*DD;
    int tid = threadIdx.x;
    float v0 = hp[tid], v1 = hp[tid+256], v2 = hp[tid+512], v3 = hp[tid+768];
    __shared__ float red[256];
    red[tid] = v0*v0 + v1*v1 + v2*v2 + v3*v3;
    __syncthreads();
    for (int o = 128; o > 0; o >>= 1) {
        if (tid < o) red[tid] += red[tid + o];
        __syncthreads();
    }
    float inv = rsqrtf(red[0] * (1.0f/DD) + 1e-6f);
    size_t o = (size_t)r*DD;
    g_ahi[o+tid]     = __float2half(v0*inv*lnw[tid]);
    g_ahi[o+tid+256] = __float2half(v1*inv*lnw[tid+256]);
    g_ahi[o+tid+512] = __float2half(v2*inv*lnw[tid+512]);
    g_ahi[o+tid+768] = __float2half(v3*inv*lnw[tid+768]);
}

// ---------------------------------------------------------------------------
// Empty-row pipeline (fp32)
// ---------------------------------------------------------------------------
__global__ void k_empty1(const float* __restrict__ cb, const float* __restrict__ lnw) {
    int tid = threadIdx.x;
    float v0 = cb[tid], v1 = cb[tid+256], v2 = cb[tid+512], v3 = cb[tid+768];
    __shared__ float red[256];
    red[tid] = v0*v0 + v1*v1 + v2*v2 + v3*v3;
    __syncthreads();
    for (int o = 128; o > 0; o >>= 1) {
        if (tid < o) red[tid] += red[tid + o];
        __syncthreads();
    }
    float inv = rsqrtf(red[0] * (1.0f/DD) + 1e-6f);
    g_embed[tid]     = v0 * inv * lnw[tid];
    g_embed[tid+256] = v1 * inv * lnw[tid+256];
    g_embed[tid+512] = v2 * inv * lnw[tid+512];
    g_embed[tid+768] = v3 * inv * lnw[tid+768];
}
__global__ void k_empty2(const float* __restrict__ tw, const float* __restrict__ tb) {
    int c = blockIdx.x;
    int tid = threadIdx.x;
    const float* wr = tw + (size_t)c*DD;
    float s = 0.f;
    #pragma unroll
    for (int i = 0; i < 4; i++)
        s += g_embed[tid + i*256] * wr[tid + i*256];
    __shared__ float red[256];
    red[tid] = s;
    __syncthreads();
    for (int o = 128; o > 0; o >>= 1) {
        if (tid < o) red[tid] += red[tid + o];
        __syncthreads();
    }
    if (tid == 0) g_outempty[c] = red[0] + tb[c];
}
__global__ void k_fill(float* __restrict__ out) {
    int r = blockIdx.x;
    int b = r / NTOK, n = r % NTOK;
    if (n < g_nt[b]) return;
    float4* dst = (float4*)(out + (size_t)r*DTXT);
    const float4* src = (const float4*)g_outempty;
    for (int i = threadIdx.x; i < DTXT/4; i += 256)
        dst[i] = src[i];
}

// ---------------------------------------------------------------------------
// fp16 tensor-core GEMM (128x128, warp 64x32, BK=32) — at HMMA ceiling.
// ---------------------------------------------------------------------------
#define AROWB     80
#define ATILEB    (128*AROWB)

__device__ __forceinline__ void cp16(uint32_t dst, const void* src) {
    asm volatile("cp.async.cg.shared.global [%0], [%1], 16;"
                 :: "r"(dst), "l"(src) : "memory");
}
__device__ __forceinline__ void ldsm4(uint32_t r[4], uint32_t addr) {
    asm volatile("ldmatrix.sync.aligned.m8n8.x4.shared.b16 {%0,%1,%2,%3}, [%4];"
                 : "=r"(r[0]), "=r"(r[1]), "=r"(r[2]), "=r"(r[3]) : "r"(addr));
}
__device__ __forceinline__ void mma_h(float d[4], const uint32_t a[4],
                                      uint32_t b0, uint32_t b1) {
    asm volatile(
        "mma.sync.aligned.m16n8k16.row.col.f32.f16.f16.f32 "
        "{%0,%1,%2,%3}, {%4,%5,%6,%7}, {%8,%9}, {%0,%1,%2,%3};"
        : "+f"(d[0]), "+f"(d[1]), "+f"(d[2]), "+f"(d[3])
        : "r"(a[0]), "r"(a[1]), "r"(a[2]), "r"(a[3]), "r"(b0), "r"(b1));
}

template<int NPASS, bool SCATTER>
__global__ void __launch_bounds__(256)
gemm_h(int K,
       const __half* __restrict__ Ah, const __half* __restrict__ Al, int lda,
       const __half* __restrict__ Bh, int ldb,
       const float* __restrict__ bias,
       float* __restrict__ C, int ldc)
{
    constexpr int NA = (NPASS == 2) ? 2 : 1;
    constexpr uint32_t STAGEB = (NA + 1) * ATILEB;
    extern __shared__ __align__(128) char smem[];
    uint32_t sbase = (uint32_t)__cvta_generic_to_shared(smem);

    int M = g_Mp[0];
    int m0 = blockIdx.y * 128;
    if (m0 >= M) return;
    int tid  = threadIdx.x;
    int wid  = tid >> 5, lane = tid & 31;
    int g    = lane >> 2, tig = lane & 3;
    int n0   = blockIdx.x * 128;
    int wm   = (wid & 1) * 64;
    int wn   = (wid >> 1) * 32;

    float acc[4][4][4];
    #pragma unroll
    for (int i = 0; i < 4; i++)
        #pragma unroll
        for (int j = 0; j < 4; j++)
            #pragma unroll
            for (int q = 0; q < 4; q++) acc[i][j][q] = 0.f;

    const int nt = K >> 5;

    auto load_stage = [&](int s, int kt) {
        uint32_t st = sbase + (uint32_t)s * STAGEB;
        int k0 = kt << 5;
        #pragma unroll
        for (int c = tid; c < 512; c += 256) {
            int row = c >> 2, ch = (c & 3) << 4;
            int ke = k0 + (ch >> 1);
            int gm = m0 + row; if (gm >= M) gm = M - 1;
            uint32_t d = st + row*AROWB + ch;
            cp16(d, Ah + (size_t)gm*lda + ke);
            if (NPASS == 2) cp16(d + ATILEB, Al + (size_t)gm*lda + ke);
            cp16(st + NA*ATILEB + row*AROWB + ch, Bh + (size_t)(n0 + row)*ldb + ke);
        }
        asm volatile("cp.async.commit_group;" ::: "memory");
    };

    load_stage(0, 0);

    int quad = lane >> 3, qr = lane & 7;
    for (int kt = 0; kt < nt; kt++) {
        int buf = kt & 1;
        if (kt + 1 < nt) {
            load_stage(buf ^ 1, kt + 1);
            asm volatile("cp.async.wait_group 1;" ::: "memory");
        } else {
            asm volatile("cp.async.wait_group 0;" ::: "memory");
        }
        __syncthreads();

        uint32_t st = sbase + (uint32_t)buf * STAGEB;
        #pragma unroll
        for (int ks = 0; ks < 2; ks++) {
            int kc = ks * 16;
            uint32_t ka = (uint32_t)((kc + ((quad >> 1) << 3)) << 1);
            uint32_t arow = st + (uint32_t)(wm + ((quad & 1) << 3) + qr) * AROWB + ka;
            uint32_t brow = st + NA*ATILEB
                          + (uint32_t)(wn + ((quad & 1) << 3) + qr) * AROWB + ka;

            uint32_t ah[4][4], al[4][4], bh[2][4];
            #pragma unroll
            for (int mi = 0; mi < 4; mi++) {
                ldsm4(ah[mi], arow + mi*16*AROWB);
                if (NPASS == 2) ldsm4(al[mi], arow + ATILEB + mi*16*AROWB);
            }
            #pragma unroll
            for (int nb = 0; nb < 2; nb++)
                ldsm4(bh[nb], brow + nb*16*AROWB);

            #pragma unroll
            for (int mi = 0; mi < 4; mi++)
                #pragma unroll
                for (int ni = 0; ni < 4; ni++) {
                    int nb = ni >> 1, sel = ni & 1;
                    mma_h(acc[mi][ni], ah[mi], bh[nb][sel], bh[nb][sel+2]);
                    if (NPASS == 2)
                        mma_h(acc[mi][ni], al[mi], bh[nb][sel], bh[nb][sel+2]);
                }
        }
        __syncthreads();
    }

    #pragma unroll
    for (int mi = 0; mi < 4; mi++) {
        int row0 = m0 + wm + mi*16 + g;
        int row1 = row0 + 8;
        int o0 = (SCATTER && row0 < M) ? g_rowmap[row0] : row0;
        int o1 = (SCATTER && row1 < M) ? g_rowmap[row1] : row1;
        #pragma unroll
        for (int ni = 0; ni < 4; ni++) {
            int col = n0 + wn + ni*8 + 2*tig;
            float b0 = bias[col], b1 = bias[col+1];
            if (row0 < M) {
                float2 v = { acc[mi][ni][0] + b0, acc[mi][ni][1] + b1 };
                *reinterpret_cast<float2*>(C + (size_t)o0*ldc + col) = v;
            }
            if (row1 < M) {
                float2 v = { acc[mi][ni][2] + b0, acc[mi][ni][3] + b1 };
                *reinterpret_cast<float2*>(C + (size_t)o1*ldc + col) = v;
            }
        }
    }
}

// ---------------------------------------------------------------------------
__global__ void k_tail(float* __restrict__ out, int out_size) {
    int i = threadIdx.x;
    if (i < BB && out_size >= MM*DTXT + 2*BB) {
        out[MM*DTXT + i]      = (float)g_nt[i];
        out[MM*DTXT + BB + i] = g_numpred[i];
    }
}

// ---------------------------------------------------------------------------
extern "C" void kernel_launch(void* const* d_in, const int* in_sizes, int n_in,
                              void* d_out, int out_size) {
    const float* af     = (const float*)d_in[0];
    const float* cif_w  = (const float*)d_in[1];
    const float* cif_b  = (const float*)d_in[2];
    const float* ln_w   = (const float*)d_in[3];
    const float* text_w = (const float*)d_in[4];
    const float* text_b = (const float*)d_in[5];
    const void*  nf     = d_in[6];
    const void*  nt     = d_in[7];
    float* out = (float*)d_out;

    void *p_h2=0, *p_ahi=0, *p_alo=0, *p_bhi=0;
    cudaGetSymbolAddress(&p_h2,  g_h2);
    cudaGetSymbolAddress(&p_ahi, g_ahi);
    cudaGetSymbolAddress(&p_alo, g_alo);
    cudaGetSymbolAddress(&p_bhi, g_bhi);

    const int SMEM2 = 2 * 3 * ATILEB;   // 61440
    const int SMEM1 = 2 * 2 * ATILEB;   // 40960
    cudaFuncSetAttribute((const void*)gemm_h<2,false>, cudaFuncAttributeMaxDynamicSharedMemorySize, SMEM2);
    cudaFuncSetAttribute((const void*)gemm_h<1,true>,  cudaFuncAttributeMaxDynamicSharedMemorySize, SMEM1);
    cudaFuncSetAttribute((const void*)k_cif8,          cudaFuncAttributeMaxDynamicSharedMemorySize, CIF_SMEM);

    k_detect<<<1, 1>>>(nf, nt);
    k_empty1<<<1, 256>>>(cif_b, ln_w);
    k_empty2<<<DTXT, 256>>>(text_w, text_b);
    k_cif8<<<1, 512, CIF_SMEM>>>(af);
    k_fill<<<MM, 256>>>(out);
    k_h1<<<MM, 256>>>(af);
    k_padw_hi<<<(DD*DD)/256, 256>>>(cif_w);

    // cif_proj (compact): 2-pass
    {
        dim3 grid(DD/128, (MM + 127)/128);
        gemm_h<2,false><<<grid, 256, SMEM2>>>(1024,
            (const __half*)p_ahi, (const __half*)p_alo, LDH,
            (const __half*)p_bhi, 1024,
            cif_b, (float*)p_h2, DD);
    }
    k_rms<<<MM, 256>>>(ln_w);
    k_w_hi<<<(DTXT*DD)/256, 256>>>(text_w);

    // text_proj (compact, scatter epilogue): 1-pass
    {
        dim3 grid(DTXT/128, (MM + 127)/128);
        gemm_h<1,true><<<grid, 256, SMEM1>>>(1024,
            (const __half*)p_ahi, (const __half*)p_alo, LDH,
            (const __half*)p_bhi, DD,
            text_b, out, DTXT);
    }
    k_tail<<<1, 32>>>(out, out_size);
}

// round 16
// speedup vs baseline: 1.3302x; 1.1253x over previous
#include <cuda_runtime.h>
#include <cuda_fp16.h>
#include <math.h>
#include <stdint.h>

#define BB   16
#define TT   1500
#define DD   1024
#define DH   1023
#define DTXT 4096
#define NTOK 375
#define MM   (BB*NTOK)     // 6000
#define MAXP 12288
#define LDH  1024

// ---------------------------------------------------------------------------
// Device scratch
// ---------------------------------------------------------------------------
__device__ float g_numpred[BB];
__device__ int   g_nf[BB];
__device__ int   g_nt[BB];
__device__ int2  g_pairs[BB*MAXP];              // [b*MAXP + p]  (R12 layout)
__device__ int   g_rowptr[BB*(NTOK+1)];
__device__ int   g_rowmap[MM];
__device__ int   g_Mp[1];
__device__ float g_h2 [(size_t)MM*DD];
__device__ __half g_ahi[(size_t)MM*LDH];
__device__ __half g_alo[(size_t)MM*LDH];
__device__ __half g_bhi[(size_t)DD*DD];         // cif_w (padded) fp16
__device__ __half g_bt [(size_t)DTXT*DD];       // text_w fp16 (separate!)
__device__ float g_embed[DD];
__device__ float g_outempty[DTXT];

__device__ __forceinline__ void split_h(float x, __half& h, __half& l) {
    h = __float2half(x);
    l = __float2half(x - __half2float(h));
}

// ---------------------------------------------------------------------------
// k_pre: int width detect + empty-row embed (rmsnorm(cif_b)*ln_w)
// ---------------------------------------------------------------------------
__global__ void k_pre(const void* nf_raw, const void* nt_raw,
                      const float* __restrict__ cb, const float* __restrict__ lnw) {
    int tid = threadIdx.x;
    if (tid == 0) {
        const int* a = (const int*)nf_raw;
        const int* b = (const int*)nt_raw;
        bool is64 = (a[1] == 0) && (a[3] == 0) && (a[5] == 0);
        for (int i = 0; i < BB; i++) {
            if (is64) {
                g_nf[i] = (int)((const long long*)nf_raw)[i];
                g_nt[i] = (int)((const long long*)nt_raw)[i];
            } else {
                g_nf[i] = a[i];
                g_nt[i] = b[i];
            }
        }
    }
    float v0 = cb[tid], v1 = cb[tid+256], v2 = cb[tid+512], v3 = cb[tid+768];
    __shared__ float red[256];
    red[tid] = v0*v0 + v1*v1 + v2*v2 + v3*v3;
    __syncthreads();
    for (int o = 128; o > 0; o >>= 1) {
        if (tid < o) red[tid] += red[tid + o];
        __syncthreads();
    }
    float inv = rsqrtf(red[0] * (1.0f/DD) + 1e-6f);
    g_embed[tid]     = v0 * inv * lnw[tid];
    g_embed[tid+256] = v1 * inv * lnw[tid+256];
    g_embed[tid+512] = v2 * inv * lnw[tid+512];
    g_embed[tid+768] = v3 * inv * lnw[tid+768];
}

// ---------------------------------------------------------------------------
// MEGA kernel: block 0 = exact R12 cif5 scan; blocks 1..32 = padw;
// blocks 33..96 = text_w convert (-> g_bt); blocks 97..160 = empty-row dots.
// ---------------------------------------------------------------------------
#define CIF_SMEM (BB*TT*4 + BB*(NTOK+1)*4)   // 120064 B
#define NB_PADW 32
#define NB_WHI  64
#define NB_E2   64
#define MEGA_BLOCKS (1 + NB_PADW + NB_WHI + NB_E2)

__global__ void __launch_bounds__(512) k_mega(
    const float* __restrict__ af,
    const float* __restrict__ cif_w,
    const float* __restrict__ text_w,
    const float* __restrict__ text_b)
{
    int bid = blockIdx.x;
    int tid = threadIdx.x;
    int w = tid >> 5, lane = tid & 31;

    if (bid == 0) {
        // ================= exact R12 cif5 scan =================
        extern __shared__ char cs[];
        float* sal   = (float*)cs;
        int*   slast = (int*)(cs + BB*TT*4);
        __shared__ int s_off[BB+1];

        // phase A: warp w = batch w
        {
            int b = w;
            int nf = g_nf[b];
            float s = 0.f;
            for (int t = lane; t < TT; t += 32) {
                float x  = af[((size_t)b*TT + t)*DD + (DD-1)];
                float sg = 1.0f / (1.0f + expf(-x));
                if (t >= nf) sg = 0.f;
                sal[b*TT + t] = sg;
                s += sg;
            }
            #pragma unroll
            for (int o = 16; o > 0; o >>= 1)
                s += __shfl_xor_sync(0xFFFFFFFFu, s, o);
            if (lane == 0) g_numpred[b] = s;
            float scale = (float)g_nt[b] / s;
            for (int t = lane; t < TT; t += 32)
                sal[b*TT + t] *= scale;
        }
        if (tid == 0) {
            s_off[0] = 0;
            for (int b = 0; b < BB; b++) s_off[b+1] = s_off[b] + g_nt[b];
            g_Mp[0] = s_off[BB];
        }
        __syncthreads();
        {
            int b = w, o = s_off[b], n_t = g_nt[b];
            for (int n = lane; n < n_t; n += 32)
                g_rowmap[o + n] = b*NTOK + n;
        }
        for (int i = tid; i < BB*(NTOK+1); i += 512) slast[i] = 0;
        __syncthreads();

        if (tid < BB) {
            const unsigned FULL = 0xFFFFu;
            int b = tid;
            const float* al = sal + b*TT;
            int* lrow = slast + b*(NTOK+1);
            int base = b * MAXP;
            int nt1 = g_nt[b] - 1;

            float integrate = 0.f;
            int idx = 0, pcnt = 0;
            float p_w0 = 0.f, p_w1 = 0.f;
            int   p_n0 = 0,   p_n1 = 0;
            bool  efire = false;

            float a = al[0];
            #pragma unroll 4
            for (int t = 0; t < TT; t++) {
                float a_next = al[(t + 1 < TT) ? t + 1 : t];
                if (t > 0) {
                    if (p_w0 != 0.f) {
                        g_pairs[base+pcnt] = make_int2(t-1, __float_as_int(p_w0));
                        lrow[p_n0] = ++pcnt;
                    }
                    if (p_w1 != 0.f) {
                        g_pairs[base+pcnt] = make_int2(t-1, __float_as_int(p_w1));
                        lrow[p_n1] = ++pcnt;
                    }
                }
                float an = 1.f - integrate;
                integrate += a;
                bool ready = (integrate >= 1.f);
                float aint = ready ? an : a;
                if (ready) integrate -= 1.f;
                p_n0 = idx; p_w0 = aint;
                p_w1 = a - aint;
                if (ready) idx = min(idx + 1, nt1);
                p_n1 = idx;
                efire |= (integrate >= 1.f);
                a = a_next;
            }
            if (p_w0 != 0.f) {
                g_pairs[base+pcnt] = make_int2(TT-1, __float_as_int(p_w0));
                lrow[p_n0] = ++pcnt;
            }

            bool slow = __any_sync(FULL, efire);
            if (slow) {
                for (int n = 0; n <= NTOK; n++) lrow[n] = 0;
                integrate = 0.f; idx = 0; pcnt = 0;
                float prem = 0.f;
                int pn[6]; float pw[6]; int pc = 0;
                for (int t = 0; t < TT; t++) {
                    if (t > 0) {
                        if (prem != 0.f) {
                            #pragma unroll
                            for (int j = 0; j < 6; j++)
                                if (j == pc) { pn[j] = idx; pw[j] = prem; }
                            if (pc < 6) pc++;
                        }
                        #pragma unroll
                        for (int i = 0; i < 6; i++) {
                            if (i < pc && pw[i] != 0.f && pcnt < MAXP) {
                                g_pairs[base+pcnt] = make_int2(t-1, __float_as_int(pw[i]));
                                lrow[pn[i]] = pcnt + 1; pcnt++;
                            }
                        }
                        pc = 0;
                    }
                    float av = al[t];
                    float an = 1.f - integrate;
                    integrate += av;
                    bool ready = (integrate >= 1.f);
                    if (ready) integrate -= 1.f;
                    float aint = ready ? an : av;
                    pn[0] = idx; pw[0] = aint; pc = 1;
                    prem = av - aint;
                    if (ready) idx = min(idx + 1, nt1);
                    #pragma unroll
                    for (int e = 0; e < 3; e++) {
                        bool any = __any_sync(FULL, integrate >= 1.f);
                        if (any) {
                            bool r2 = (integrate >= 1.f);
                            if (r2) integrate -= 1.f;
                            float ai2 = r2 ? 1.f : prem;
                            bool found = false;
                            #pragma unroll
                            for (int j = 0; j < 6; j++)
                                if (j < pc && pn[j] == idx && !found) { pw[j] = ai2; found = true; }
                            if (!found) {
                                #pragma unroll
                                for (int j = 0; j < 6; j++)
                                    if (j == pc) { pn[j] = idx; pw[j] = ai2; }
                                if (pc < 6) pc++;
                            }
                            prem = prem - ai2;
                            if (r2) idx = min(idx + 1, nt1);
                        }
                    }
                }
                #pragma unroll
                for (int i = 0; i < 6; i++) {
                    if (i < pc && pw[i] != 0.f && pcnt < MAXP) {
                        g_pairs[base+pcnt] = make_int2(TT-1, __float_as_int(pw[i]));
                        lrow[pn[i]] = pcnt + 1; pcnt++;
                    }
                }
            } else {
                __any_sync(FULL, false);
            }

            int* rp = &g_rowptr[b*(NTOK+1)];
            rp[0] = 0;
            int p = 0;
            for (int n = 0; n < NTOK; n++) {
                int v = lrow[n];
                if (v > 0) p = v;
                rp[n+1] = p;
            }
        }
    } else if (bid <= NB_PADW) {
        // ================= pad+convert cif_w -> g_bhi =================
        int j = bid - 1;
        for (int i = j*512 + tid; i < DD*DD; i += NB_PADW*512) {
            int n = i >> 10, k = i & 1023;
            float v = (k < DH) ? cif_w[(size_t)n*DH + k] : 0.f;
            g_bhi[i] = __float2half(v);
        }
    } else if (bid <= NB_PADW + NB_WHI) {
        // ================= convert text_w -> g_bt =================
        int j = bid - 1 - NB_PADW;
        for (int i = j*512 + tid; i < DTXT*DD; i += NB_WHI*512) {
            g_bt[i] = __float2half(text_w[i]);
        }
    } else {
        // ================= empty-row output dots =================
        int j = bid - 1 - NB_PADW - NB_WHI;      // 0..63
        // 16 warps x 4 columns each = 64 columns per block
        #pragma unroll
        for (int i = 0; i < 4; i++) {
            int c = j*64 + w*4 + i;
            const float* wr = text_w + (size_t)c*DD;
            float s = 0.f;
            #pragma unroll
            for (int k2 = 0; k2 < 32; k2++)
                s += g_embed[lane + k2*32] * wr[lane + k2*32];
            #pragma unroll
            for (int o = 16; o > 0; o >>= 1)
                s += __shfl_xor_sync(0xFFFFFFFFu, s, o);
            if (lane == 0) g_outempty[c] = s + text_b[c];
        }
    }
}

// ---------------------------------------------------------------------------
// k_fill: broadcast empty-row output to all (b, n>=nt[b]) rows
// ---------------------------------------------------------------------------
__global__ void k_fill(float* __restrict__ out) {
    int r = blockIdx.x;
    int b = r / NTOK, n = r % NTOK;
    if (n < g_nt[b]) return;
    float4* dst = (float4*)(out + (size_t)r*DTXT);
    const float4* src = (const float4*)g_outempty;
    for (int i = threadIdx.x; i < DTXT/4; i += 256)
        dst[i] = src[i];
}

// ---------------------------------------------------------------------------
// k_h1 (compact, R12 layout)
// ---------------------------------------------------------------------------
__global__ void k_h1(const float* __restrict__ af) {
    int r = blockIdx.x;
    if (r >= g_Mp[0]) return;
    int bn = g_rowmap[r];
    int b = bn / NTOK, n = bn % NTOK;
    int s = g_rowptr[b*(NTOK+1) + n];
    int e = g_rowptr[b*(NTOK+1) + n + 1];
    int d = threadIdx.x;
    float a0 = 0.f, a1 = 0.f, a2 = 0.f, a3 = 0.f;
    for (int p = s; p < e; p++) {
        int2 pr = g_pairs[b*MAXP + p];
        int   t = pr.x;
        float w = __int_as_float(pr.y);
        const float* row = af + ((size_t)b*TT + t)*DD;
        a0 += w * row[d];
        a1 += w * row[d + 256];
        a2 += w * row[d + 512];
        if (d + 768 < DH) a3 += w * row[d + 768];
    }
    size_t o = (size_t)r*LDH;
    __half h, l;
    split_h(a0, h, l); g_ahi[o+d]     = h; g_alo[o+d]     = l;
    split_h(a1, h, l); g_ahi[o+d+256] = h; g_alo[o+d+256] = l;
    split_h(a2, h, l); g_ahi[o+d+512] = h; g_alo[o+d+512] = l;
    if (d + 768 < DH) { split_h(a3, h, l); g_ahi[o+d+768] = h; g_alo[o+d+768] = l; }
    else { g_ahi[o+1023] = __float2half(0.f); g_alo[o+1023] = __float2half(0.f); }
}

// ---------------------------------------------------------------------------
__global__ void k_rms(const float* __restrict__ lnw) {
    int r = blockIdx.x;
    if (r >= g_Mp[0]) return;
    const float* hp = g_h2 + (size_t)r*DD;
    int tid = threadIdx.x;
    float v0 = hp[tid], v1 = hp[tid+256], v2 = hp[tid+512], v3 = hp[tid+768];
    __shared__ float red[256];
    red[tid] = v0*v0 + v1*v1 + v2*v2 + v3*v3;
    __syncthreads();
    for (int o = 128; o > 0; o >>= 1) {
        if (tid < o) red[tid] += red[tid + o];
        __syncthreads();
    }
    float inv = rsqrtf(red[0] * (1.0f/DD) + 1e-6f);
    size_t o = (size_t)r*DD;
    g_ahi[o+tid]     = __float2half(v0*inv*lnw[tid]);
    g_ahi[o+tid+256] = __float2half(v1*inv*lnw[tid+256]);
    g_ahi[o+tid+512] = __float2half(v2*inv*lnw[tid+512]);
    g_ahi[o+tid+768] = __float2half(v3*inv*lnw[tid+768]);
}

// ---------------------------------------------------------------------------
// fp16 tensor-core GEMM (128x128, warp 64x32, BK=32) — R12 exact
// ---------------------------------------------------------------------------
#define AROWB     80
#define ATILEB    (128*AROWB)

__device__ __forceinline__ void cp16(uint32_t dst, const void* src) {
    asm volatile("cp.async.cg.shared.global [%0], [%1], 16;"
                 :: "r"(dst), "l"(src) : "memory");
}
__device__ __forceinline__ void ldsm4(uint32_t r[4], uint32_t addr) {
    asm volatile("ldmatrix.sync.aligned.m8n8.x4.shared.b16 {%0,%1,%2,%3}, [%4];"
                 : "=r"(r[0]), "=r"(r[1]), "=r"(r[2]), "=r"(r[3]) : "r"(addr));
}
__device__ __forceinline__ void mma_h(float d[4], const uint32_t a[4],
                                      uint32_t b0, uint32_t b1) {
    asm volatile(
        "mma.sync.aligned.m16n8k16.row.col.f32.f16.f16.f32 "
        "{%0,%1,%2,%3}, {%4,%5,%6,%7}, {%8,%9}, {%0,%1,%2,%3};"
        : "+f"(d[0]), "+f"(d[1]), "+f"(d[2]), "+f"(d[3])
        : "r"(a[0]), "r"(a[1]), "r"(a[2]), "r"(a[3]), "r"(b0), "r"(b1));
}

template<int NPASS, bool SCATTER>
__global__ void __launch_bounds__(256)
gemm_h(int K,
       const __half* __restrict__ Ah, const __half* __restrict__ Al, int lda,
       const __half* __restrict__ Bh, int ldb,
       const float* __restrict__ bias,
       float* __restrict__ C, int ldc)
{
    constexpr int NA = (NPASS == 2) ? 2 : 1;
    constexpr uint32_t STAGEB = (NA + 1) * ATILEB;
    extern __shared__ __align__(128) char smem[];
    uint32_t sbase = (uint32_t)__cvta_generic_to_shared(smem);

    int M = g_Mp[0];
    int m0 = blockIdx.y * 128;
    if (m0 >= M) return;
    int tid  = threadIdx.x;
    int wid  = tid >> 5, lane = tid & 31;
    int g    = lane >> 2, tig = lane & 3;
    int n0   = blockIdx.x * 128;
    int wm   = (wid & 1) * 64;
    int wn   = (wid >> 1) * 32;

    float acc[4][4][4];
    #pragma unroll
    for (int i = 0; i < 4; i++)
        #pragma unroll
        for (int j = 0; j < 4; j++)
            #pragma unroll
            for (int q = 0; q < 4; q++) acc[i][j][q] = 0.f;

    const int nt = K >> 5;

    auto load_stage = [&](int s, int kt) {
        uint32_t st = sbase + (uint32_t)s * STAGEB;
        int k0 = kt << 5;
        #pragma unroll
        for (int c = tid; c < 512; c += 256) {
            int row = c >> 2, ch = (c & 3) << 4;
            int ke = k0 + (ch >> 1);
            int gm = m0 + row; if (gm >= M) gm = M - 1;
            uint32_t d = st + row*AROWB + ch;
            cp16(d, Ah + (size_t)gm*lda + ke);
            if (NPASS == 2) cp16(d + ATILEB, Al + (size_t)gm*lda + ke);
            cp16(st + NA*ATILEB + row*AROWB + ch, Bh + (size_t)(n0 + row)*ldb + ke);
        }
        asm volatile("cp.async.commit_group;" ::: "memory");
    };

    load_stage(0, 0);

    int quad = lane >> 3, qr = lane & 7;
    for (int kt = 0; kt < nt; kt++) {
        int buf = kt & 1;
        if (kt + 1 < nt) {
            load_stage(buf ^ 1, kt + 1);
            asm volatile("cp.async.wait_group 1;" ::: "memory");
        } else {
            asm volatile("cp.async.wait_group 0;" ::: "memory");
        }
        __syncthreads();

        uint32_t st = sbase + (uint32_t)buf * STAGEB;
        #pragma unroll
        for (int ks = 0; ks < 2; ks++) {
            int kc = ks * 16;
            uint32_t ka = (uint32_t)((kc + ((quad >> 1) << 3)) << 1);
            uint32_t arow = st + (uint32_t)(wm + ((quad & 1) << 3) + qr) * AROWB + ka;
            uint32_t brow = st + NA*ATILEB
                          + (uint32_t)(wn + ((quad & 1) << 3) + qr) * AROWB + ka;

            uint32_t ah[4][4], al[4][4], bh[2][4];
            #pragma unroll
            for (int mi = 0; mi < 4; mi++) {
                ldsm4(ah[mi], arow + mi*16*AROWB);
                if (NPASS == 2) ldsm4(al[mi], arow + ATILEB + mi*16*AROWB);
            }
            #pragma unroll
            for (int nb = 0; nb < 2; nb++)
                ldsm4(bh[nb], brow + nb*16*AROWB);

            #pragma unroll
            for (int mi = 0; mi < 4; mi++)
                #pragma unroll
                for (int ni = 0; ni < 4; ni++) {
                    int nb = ni >> 1, sel = ni & 1;
                    mma_h(acc[mi][ni], ah[mi], bh[nb][sel], bh[nb][sel+2]);
                    if (NPASS == 2)
                        mma_h(acc[mi][ni], al[mi], bh[nb][sel], bh[nb][sel+2]);
                }
        }
        __syncthreads();
    }

    #pragma unroll
    for (int mi = 0; mi < 4; mi++) {
        int row0 = m0 + wm + mi*16 + g;
        int row1 = row0 + 8;
        int o0 = (SCATTER && row0 < M) ? g_rowmap[row0] : row0;
        int o1 = (SCATTER && row1 < M) ? g_rowmap[row1] : row1;
        #pragma unroll
        for (int ni = 0; ni < 4; ni++) {
            int col = n0 + wn + ni*8 + 2*tig;
            float b0 = bias[col], b1 = bias[col+1];
            if (row0 < M) {
                float2 v = { acc[mi][ni][0] + b0, acc[mi][ni][1] + b1 };
                *reinterpret_cast<float2*>(C + (size_t)o0*ldc + col) = v;
            }
            if (row1 < M) {
                float2 v = { acc[mi][ni][2] + b0, acc[mi][ni][3] + b1 };
                *reinterpret_cast<float2*>(C + (size_t)o1*ldc + col) = v;
            }
        }
    }
}

// ---------------------------------------------------------------------------
__global__ void k_tail(float* __restrict__ out, int out_size) {
    int i = threadIdx.x;
    if (i < BB && out_size >= MM*DTXT + 2*BB) {
        out[MM*DTXT + i]      = (float)g_nt[i];
        out[MM*DTXT + BB + i] = g_numpred[i];
    }
}

// ---------------------------------------------------------------------------
extern "C" void kernel_launch(void* const* d_in, const int* in_sizes, int n_in,
                              void* d_out, int out_size) {
    const float* af     = (const float*)d_in[0];
    const float* cif_w  = (const float*)d_in[1];
    const float* cif_b  = (const float*)d_in[2];
    const float* ln_w   = (const float*)d_in[3];
    const float* text_w = (const float*)d_in[4];
    const float* text_b = (const float*)d_in[5];
    const void*  nf     = d_in[6];
    const void*  nt     = d_in[7];
    float* out = (float*)d_out;

    void *p_h2=0, *p_ahi=0, *p_alo=0, *p_bhi=0, *p_bt=0;
    cudaGetSymbolAddress(&p_h2,  g_h2);
    cudaGetSymbolAddress(&p_ahi, g_ahi);
    cudaGetSymbolAddress(&p_alo, g_alo);
    cudaGetSymbolAddress(&p_bhi, g_bhi);
    cudaGetSymbolAddress(&p_bt,  g_bt);

    const int SMEM2 = 2 * 3 * ATILEB;   // 61440
    const int SMEM1 = 2 * 2 * ATILEB;   // 40960
    cudaFuncSetAttribute((const void*)gemm_h<2,false>, cudaFuncAttributeMaxDynamicSharedMemorySize, SMEM2);
    cudaFuncSetAttribute((const void*)gemm_h<1,true>,  cudaFuncAttributeMaxDynamicSharedMemorySize, SMEM1);
    cudaFuncSetAttribute((const void*)k_mega,          cudaFuncAttributeMaxDynamicSharedMemorySize, CIF_SMEM);

    k_pre<<<1, 256>>>(nf, nt, cif_b, ln_w);
    k_mega<<<MEGA_BLOCKS, 512, CIF_SMEM>>>(af, cif_w, text_w, text_b);
    k_fill<<<MM, 256>>>(out);
    k_h1<<<MM, 256>>>(af);

    // cif_proj (compact): 2-pass
    {
        dim3 grid(DD/128, (MM + 127)/128);
        gemm_h<2,false><<<grid, 256, SMEM2>>>(1024,
            (const __half*)p_ahi, (const __half*)p_alo, LDH,
            (const __half*)p_bhi, 1024,
            cif_b, (float*)p_h2, DD);
    }
    k_rms<<<MM, 256>>>(ln_w);

    // text_proj (compact, scatter epilogue): 1-pass, B = g_bt
    {
        dim3 grid(DTXT/128, (MM + 127)/128);
        gemm_h<1,true><<<grid, 256, SMEM1>>>(1024,
            (const __half*)p_ahi, (const __half*)p_alo, LDH,
            (const __half*)p_bt, DD,
            text_b, out, DTXT);
    }
    k_tail<<<1, 32>>>(out, out_size);
}

// round 17
// speedup vs baseline: 1.4881x; 1.1187x over previous
#include <cuda_runtime.h>
#include <cuda_fp16.h>
#include <math.h>
#include <stdint.h>

#define BB   16
#define TT   1500
#define DD   1024
#define DH   1023
#define DTXT 4096
#define NTOK 375
#define MM   (BB*NTOK)     // 6000
#define MAXP 12288
#define LDH  1024

// ---------------------------------------------------------------------------
// Device scratch
// ---------------------------------------------------------------------------
__device__ float g_numpred[BB];
__device__ int   g_nf[BB];
__device__ int   g_nt[BB];
__device__ int2  g_pairs[BB*MAXP];
__device__ int   g_rowptr[BB*(NTOK+1)];
__device__ int   g_rowmap[MM];
__device__ int   g_Mp[1];
__device__ float g_h2 [(size_t)MM*DD];
__device__ __half g_ahi[(size_t)MM*LDH];
__device__ __half g_bhi[(size_t)DD*DD];         // cif_w (padded) fp16
__device__ __half g_bt [(size_t)DTXT*DD];       // text_w fp16
__device__ float g_embed[DD];
__device__ float g_outempty[DTXT];

// ---------------------------------------------------------------------------
// k_pre: int width detect + empty-row embed (rmsnorm(cif_b)*ln_w)
// ---------------------------------------------------------------------------
__global__ void k_pre(const void* nf_raw, const void* nt_raw,
                      const float* __restrict__ cb, const float* __restrict__ lnw) {
    int tid = threadIdx.x;
    if (tid == 0) {
        const int* a = (const int*)nf_raw;
        const int* b = (const int*)nt_raw;
        bool is64 = (a[1] == 0) && (a[3] == 0) && (a[5] == 0);
        for (int i = 0; i < BB; i++) {
            if (is64) {
                g_nf[i] = (int)((const long long*)nf_raw)[i];
                g_nt[i] = (int)((const long long*)nt_raw)[i];
            } else {
                g_nf[i] = a[i];
                g_nt[i] = b[i];
            }
        }
    }
    float v0 = cb[tid], v1 = cb[tid+256], v2 = cb[tid+512], v3 = cb[tid+768];
    __shared__ float red[256];
    red[tid] = v0*v0 + v1*v1 + v2*v2 + v3*v3;
    __syncthreads();
    for (int o = 128; o > 0; o >>= 1) {
        if (tid < o) red[tid] += red[tid + o];
        __syncthreads();
    }
    float inv = rsqrtf(red[0] * (1.0f/DD) + 1e-6f);
    g_embed[tid]     = v0 * inv * lnw[tid];
    g_embed[tid+256] = v1 * inv * lnw[tid+256];
    g_embed[tid+512] = v2 * inv * lnw[tid+512];
    g_embed[tid+768] = v3 * inv * lnw[tid+768];
}

// ---------------------------------------------------------------------------
// MEGA kernel: block 0 = exact R12 cif5 scan; blocks 1..32 = padw;
// blocks 33..96 = text_w convert (-> g_bt); blocks 97..160 = empty-row dots.
// ---------------------------------------------------------------------------
#define CIF_SMEM (BB*TT*4 + BB*(NTOK+1)*4)   // 120064 B
#define NB_PADW 32
#define NB_WHI  64
#define NB_E2   64
#define MEGA_BLOCKS (1 + NB_PADW + NB_WHI + NB_E2)

__global__ void __launch_bounds__(512) k_mega(
    const float* __restrict__ af,
    const float* __restrict__ cif_w,
    const float* __restrict__ text_w,
    const float* __restrict__ text_b)
{
    int bid = blockIdx.x;
    int tid = threadIdx.x;
    int w = tid >> 5, lane = tid & 31;

    if (bid == 0) {
        // ================= exact R12 cif5 scan =================
        extern __shared__ char cs[];
        float* sal   = (float*)cs;
        int*   slast = (int*)(cs + BB*TT*4);
        __shared__ int s_off[BB+1];

        {
            int b = w;
            int nf = g_nf[b];
            float s = 0.f;
            for (int t = lane; t < TT; t += 32) {
                float x  = af[((size_t)b*TT + t)*DD + (DD-1)];
                float sg = 1.0f / (1.0f + expf(-x));
                if (t >= nf) sg = 0.f;
                sal[b*TT + t] = sg;
                s += sg;
            }
            #pragma unroll
            for (int o = 16; o > 0; o >>= 1)
                s += __shfl_xor_sync(0xFFFFFFFFu, s, o);
            if (lane == 0) g_numpred[b] = s;
            float scale = (float)g_nt[b] / s;
            for (int t = lane; t < TT; t += 32)
                sal[b*TT + t] *= scale;
        }
        if (tid == 0) {
            s_off[0] = 0;
            for (int b = 0; b < BB; b++) s_off[b+1] = s_off[b] + g_nt[b];
            g_Mp[0] = s_off[BB];
        }
        __syncthreads();
        {
            int b = w, o = s_off[b], n_t = g_nt[b];
            for (int n = lane; n < n_t; n += 32)
                g_rowmap[o + n] = b*NTOK + n;
        }
        for (int i = tid; i < BB*(NTOK+1); i += 512) slast[i] = 0;
        __syncthreads();

        if (tid < BB) {
            const unsigned FULL = 0xFFFFu;
            int b = tid;
            const float* al = sal + b*TT;
            int* lrow = slast + b*(NTOK+1);
            int base = b * MAXP;
            int nt1 = g_nt[b] - 1;

            float integrate = 0.f;
            int idx = 0, pcnt = 0;
            float p_w0 = 0.f, p_w1 = 0.f;
            int   p_n0 = 0,   p_n1 = 0;
            bool  efire = false;

            float a = al[0];
            #pragma unroll 4
            for (int t = 0; t < TT; t++) {
                float a_next = al[(t + 1 < TT) ? t + 1 : t];
                if (t > 0) {
                    if (p_w0 != 0.f) {
                        g_pairs[base+pcnt] = make_int2(t-1, __float_as_int(p_w0));
                        lrow[p_n0] = ++pcnt;
                    }
                    if (p_w1 != 0.f) {
                        g_pairs[base+pcnt] = make_int2(t-1, __float_as_int(p_w1));
                        lrow[p_n1] = ++pcnt;
                    }
                }
                float an = 1.f - integrate;
                integrate += a;
                bool ready = (integrate >= 1.f);
                float aint = ready ? an : a;
                if (ready) integrate -= 1.f;
                p_n0 = idx; p_w0 = aint;
                p_w1 = a - aint;
                if (ready) idx = min(idx + 1, nt1);
                p_n1 = idx;
                efire |= (integrate >= 1.f);
                a = a_next;
            }
            if (p_w0 != 0.f) {
                g_pairs[base+pcnt] = make_int2(TT-1, __float_as_int(p_w0));
                lrow[p_n0] = ++pcnt;
            }

            bool slow = __any_sync(FULL, efire);
            if (slow) {
                for (int n = 0; n <= NTOK; n++) lrow[n] = 0;
                integrate = 0.f; idx = 0; pcnt = 0;
                float prem = 0.f;
                int pn[6]; float pw[6]; int pc = 0;
                for (int t = 0; t < TT; t++) {
                    if (t > 0) {
                        if (prem != 0.f) {
                            #pragma unroll
                            for (int j = 0; j < 6; j++)
                                if (j == pc) { pn[j] = idx; pw[j] = prem; }
                            if (pc < 6) pc++;
                        }
                        #pragma unroll
                        for (int i = 0; i < 6; i++) {
                            if (i < pc && pw[i] != 0.f && pcnt < MAXP) {
                                g_pairs[base+pcnt] = make_int2(t-1, __float_as_int(pw[i]));
                                lrow[pn[i]] = pcnt + 1; pcnt++;
                            }
                        }
                        pc = 0;
                    }
                    float av = al[t];
                    float an = 1.f - integrate;
                    integrate += av;
                    bool ready = (integrate >= 1.f);
                    if (ready) integrate -= 1.f;
                    float aint = ready ? an : av;
                    pn[0] = idx; pw[0] = aint; pc = 1;
                    prem = av - aint;
                    if (ready) idx = min(idx + 1, nt1);
                    #pragma unroll
                    for (int e = 0; e < 3; e++) {
                        bool any = __any_sync(FULL, integrate >= 1.f);
                        if (any) {
                            bool r2 = (integrate >= 1.f);
                            if (r2) integrate -= 1.f;
                            float ai2 = r2 ? 1.f : prem;
                            bool found = false;
                            #pragma unroll
                            for (int j = 0; j < 6; j++)
                                if (j < pc && pn[j] == idx && !found) { pw[j] = ai2; found = true; }
                            if (!found) {
                                #pragma unroll
                                for (int j = 0; j < 6; j++)
                                    if (j == pc) { pn[j] = idx; pw[j] = ai2; }
                                if (pc < 6) pc++;
                            }
                            prem = prem - ai2;
                            if (r2) idx = min(idx + 1, nt1);
                        }
                    }
                }
                #pragma unroll
                for (int i = 0; i < 6; i++) {
                    if (i < pc && pw[i] != 0.f && pcnt < MAXP) {
                        g_pairs[base+pcnt] = make_int2(TT-1, __float_as_int(pw[i]));
                        lrow[pn[i]] = pcnt + 1; pcnt++;
                    }
                }
            } else {
                __any_sync(FULL, false);
            }

            int* rp = &g_rowptr[b*(NTOK+1)];
            rp[0] = 0;
            int p = 0;
            for (int n = 0; n < NTOK; n++) {
                int v = lrow[n];
                if (v > 0) p = v;
                rp[n+1] = p;
            }
        }
    } else if (bid <= NB_PADW) {
        int j = bid - 1;
        for (int i = j*512 + tid; i < DD*DD; i += NB_PADW*512) {
            int n = i >> 10, k = i & 1023;
            float v = (k < DH) ? cif_w[(size_t)n*DH + k] : 0.f;
            g_bhi[i] = __float2half(v);
        }
    } else if (bid <= NB_PADW + NB_WHI) {
        int j = bid - 1 - NB_PADW;
        for (int i = j*512 + tid; i < DTXT*DD; i += NB_WHI*512) {
            g_bt[i] = __float2half(text_w[i]);
        }
    } else {
        int j = bid - 1 - NB_PADW - NB_WHI;
        #pragma unroll
        for (int i = 0; i < 4; i++) {
            int c = j*64 + w*4 + i;
            const float* wr = text_w + (size_t)c*DD;
            float s = 0.f;
            #pragma unroll
            for (int k2 = 0; k2 < 32; k2++)
                s += g_embed[lane + k2*32] * wr[lane + k2*32];
            #pragma unroll
            for (int o = 16; o > 0; o >>= 1)
                s += __shfl_xor_sync(0xFFFFFFFFu, s, o);
            if (lane == 0) g_outempty[c] = s + text_b[c];
        }
    }
}

// ---------------------------------------------------------------------------
// k_h1fill: block r does CIF gather (compact rows) OR empty-row fill.
// h1 writes fp16 hi only (cif_proj is now 1-pass).
// ---------------------------------------------------------------------------
__global__ void k_h1fill(const float* __restrict__ af, float* __restrict__ out) {
    int r = blockIdx.x;
    int d = threadIdx.x;
    if (r >= g_Mp[0]) {
        // fill role: handle row (r - Mp)'th empty row? Simpler: use direct id.
        // Map blocks [Mp, MM) onto the empty rows in order.
        int er = r - g_Mp[0];
        // find the er-th empty row: iterate batches (BB small)
        int b = 0, cum = 0;
        #pragma unroll
        for (int i = 0; i < BB; i++) {
            int cnt = NTOK - g_nt[i];
            if (er < cum + cnt) { b = i; break; }
            cum += cnt;
        }
        int n = g_nt[b] + (er - cum);
        int row = b*NTOK + n;
        float4* dst = (float4*)(out + (size_t)row*DTXT);
        const float4* src = (const float4*)g_outempty;
        for (int i = d; i < DTXT/4; i += 256)
            dst[i] = src[i];
        return;
    }
    int bn = g_rowmap[r];
    int b = bn / NTOK, n = bn % NTOK;
    int s = g_rowptr[b*(NTOK+1) + n];
    int e = g_rowptr[b*(NTOK+1) + n + 1];
    float a0 = 0.f, a1 = 0.f, a2 = 0.f, a3 = 0.f;
    for (int p = s; p < e; p++) {
        int2 pr = g_pairs[b*MAXP + p];
        float w = __int_as_float(pr.y);
        const float* row = af + ((size_t)b*TT + pr.x)*DD;
        a0 += w * row[d];
        a1 += w * row[d + 256];
        a2 += w * row[d + 512];
        if (d + 768 < DH) a3 += w * row[d + 768];
    }
    size_t o = (size_t)r*LDH;
    g_ahi[o+d]     = __float2half(a0);
    g_ahi[o+d+256] = __float2half(a1);
    g_ahi[o+d+512] = __float2half(a2);
    g_ahi[o+d+768] = (d + 768 < DH) ? __float2half(a3) : __float2half(0.f);
}

// ---------------------------------------------------------------------------
// k_rms (+ folded tail outputs in block 0)
// ---------------------------------------------------------------------------
__global__ void k_rms(const float* __restrict__ lnw, float* __restrict__ out, int out_size) {
    int r = blockIdx.x;
    int tid = threadIdx.x;
    if (r == 0 && tid < BB && out_size >= MM*DTXT + 2*BB) {
        out[MM*DTXT + tid]      = (float)g_nt[tid];
        out[MM*DTXT + BB + tid] = g_numpred[tid];
    }
    if (r >= g_Mp[0]) return;
    const float* hp = g_h2 + (size_t)r*DD;
    float v0 = hp[tid], v1 = hp[tid+256], v2 = hp[tid+512], v3 = hp[tid+768];
    __shared__ float red[256];
    red[tid] = v0*v0 + v1*v1 + v2*v2 + v3*v3;
    __syncthreads();
    for (int o = 128; o > 0; o >>= 1) {
        if (tid < o) red[tid] += red[tid + o];
        __syncthreads();
    }
    float inv = rsqrtf(red[0] * (1.0f/DD) + 1e-6f);
    size_t o = (size_t)r*DD;
    g_ahi[o+tid]     = __float2half(v0*inv*lnw[tid]);
    g_ahi[o+tid+256] = __float2half(v1*inv*lnw[tid+256]);
    g_ahi[o+tid+512] = __float2half(v2*inv*lnw[tid+512]);
    g_ahi[o+tid+768] = __float2half(v3*inv*lnw[tid+768]);
}

// ---------------------------------------------------------------------------
// fp16 tensor-core GEMM (128x128, warp 64x32, BK=32) — 1-pass only now.
// ---------------------------------------------------------------------------
#define AROWB     80
#define ATILEB    (128*AROWB)

__device__ __forceinline__ void cp16(uint32_t dst, const void* src) {
    asm volatile("cp.async.cg.shared.global [%0], [%1], 16;"
                 :: "r"(dst), "l"(src) : "memory");
}
__device__ __forceinline__ void ldsm4(uint32_t r[4], uint32_t addr) {
    asm volatile("ldmatrix.sync.aligned.m8n8.x4.shared.b16 {%0,%1,%2,%3}, [%4];"
                 : "=r"(r[0]), "=r"(r[1]), "=r"(r[2]), "=r"(r[3]) : "r"(addr));
}
__device__ __forceinline__ void mma_h(float d[4], const uint32_t a[4],
                                      uint32_t b0, uint32_t b1) {
    asm volatile(
        "mma.sync.aligned.m16n8k16.row.col.f32.f16.f16.f32 "
        "{%0,%1,%2,%3}, {%4,%5,%6,%7}, {%8,%9}, {%0,%1,%2,%3};"
        : "+f"(d[0]), "+f"(d[1]), "+f"(d[2]), "+f"(d[3])
        : "r"(a[0]), "r"(a[1]), "r"(a[2]), "r"(a[3]), "r"(b0), "r"(b1));
}

template<bool SCATTER>
__global__ void __launch_bounds__(256)
gemm_h(int K,
       const __half* __restrict__ Ah, int lda,
       const __half* __restrict__ Bh, int ldb,
       const float* __restrict__ bias,
       float* __restrict__ C, int ldc)
{
    constexpr uint32_t STAGEB = 2 * ATILEB;
    extern __shared__ __align__(128) char smem[];
    uint32_t sbase = (uint32_t)__cvta_generic_to_shared(smem);

    int M = g_Mp[0];
    int m0 = blockIdx.y * 128;
    if (m0 >= M) return;
    int tid  = threadIdx.x;
    int wid  = tid >> 5, lane = tid & 31;
    int g    = lane >> 2, tig = lane & 3;
    int n0   = blockIdx.x * 128;
    int wm   = (wid & 1) * 64;
    int wn   = (wid >> 1) * 32;

    float acc[4][4][4];
    #pragma unroll
    for (int i = 0; i < 4; i++)
        #pragma unroll
        for (int j = 0; j < 4; j++)
            #pragma unroll
            for (int q = 0; q < 4; q++) acc[i][j][q] = 0.f;

    const int nt = K >> 5;

    auto load_stage = [&](int s, int kt) {
        uint32_t st = sbase + (uint32_t)s * STAGEB;
        int k0 = kt << 5;
        #pragma unroll
        for (int c = tid; c < 512; c += 256) {
            int row = c >> 2, ch = (c & 3) << 4;
            int ke = k0 + (ch >> 1);
            int gm = m0 + row; if (gm >= M) gm = M - 1;
            cp16(st + row*AROWB + ch, Ah + (size_t)gm*lda + ke);
            cp16(st + ATILEB + row*AROWB + ch, Bh + (size_t)(n0 + row)*ldb + ke);
        }
        asm volatile("cp.async.commit_group;" ::: "memory");
    };

    load_stage(0, 0);

    int quad = lane >> 3, qr = lane & 7;
    for (int kt = 0; kt < nt; kt++) {
        int buf = kt & 1;
        if (kt + 1 < nt) {
            load_stage(buf ^ 1, kt + 1);
            asm volatile("cp.async.wait_group 1;" ::: "memory");
        } else {
            asm volatile("cp.async.wait_group 0;" ::: "memory");
        }
        __syncthreads();

        uint32_t st = sbase + (uint32_t)buf * STAGEB;
        #pragma unroll
        for (int ks = 0; ks < 2; ks++) {
            int kc = ks * 16;
            uint32_t ka = (uint32_t)((kc + ((quad >> 1) << 3)) << 1);
            uint32_t arow = st + (uint32_t)(wm + ((quad & 1) << 3) + qr) * AROWB + ka;
            uint32_t brow = st + ATILEB
                          + (uint32_t)(wn + ((quad & 1) << 3) + qr) * AROWB + ka;

            uint32_t ah[4][4], bh[2][4];
            #pragma unroll
            for (int mi = 0; mi < 4; mi++)
                ldsm4(ah[mi], arow + mi*16*AROWB);
            #pragma unroll
            for (int nb = 0; nb < 2; nb++)
                ldsm4(bh[nb], brow + nb*16*AROWB);

            #pragma unroll
            for (int mi = 0; mi < 4; mi++)
                #pragma unroll
                for (int ni = 0; ni < 4; ni++) {
                    int nb = ni >> 1, sel = ni & 1;
                    mma_h(acc[mi][ni], ah[mi], bh[nb][sel], bh[nb][sel+2]);
                }
        }
        __syncthreads();
    }

    #pragma unroll
    for (int mi = 0; mi < 4; mi++) {
        int row0 = m0 + wm + mi*16 + g;
        int row1 = row0 + 8;
        int o0 = (SCATTER && row0 < M) ? g_rowmap[row0] : row0;
        int o1 = (SCATTER && row1 < M) ? g_rowmap[row1] : row1;
        #pragma unroll
        for (int ni = 0; ni < 4; ni++) {
            int col = n0 + wn + ni*8 + 2*tig;
            float b0 = bias[col], b1 = bias[col+1];
            if (row0 < M) {
                float2 v = { acc[mi][ni][0] + b0, acc[mi][ni][1] + b1 };
                *reinterpret_cast<float2*>(C + (size_t)o0*ldc + col) = v;
            }
            if (row1 < M) {
                float2 v = { acc[mi][ni][2] + b0, acc[mi][ni][3] + b1 };
                *reinterpret_cast<float2*>(C + (size_t)o1*ldc + col) = v;
            }
        }
    }
}

// ---------------------------------------------------------------------------
extern "C" void kernel_launch(void* const* d_in, const int* in_sizes, int n_in,
                              void* d_out, int out_size) {
    const float* af     = (const float*)d_in[0];
    const float* cif_w  = (const float*)d_in[1];
    const float* cif_b  = (const float*)d_in[2];
    const float* ln_w   = (const float*)d_in[3];
    const float* text_w = (const float*)d_in[4];
    const float* text_b = (const float*)d_in[5];
    const void*  nf     = d_in[6];
    const void*  nt     = d_in[7];
    float* out = (float*)d_out;

    void *p_h2=0, *p_ahi=0, *p_bhi=0, *p_bt=0;
    cudaGetSymbolAddress(&p_h2,  g_h2);
    cudaGetSymbolAddress(&p_ahi, g_ahi);
    cudaGetSymbolAddress(&p_bhi, g_bhi);
    cudaGetSymbolAddress(&p_bt,  g_bt);

    const int SMEM1 = 2 * 2 * ATILEB;   // 40960
    cudaFuncSetAttribute((const void*)gemm_h<false>, cudaFuncAttributeMaxDynamicSharedMemorySize, SMEM1);
    cudaFuncSetAttribute((const void*)gemm_h<true>,  cudaFuncAttributeMaxDynamicSharedMemorySize, SMEM1);
    cudaFuncSetAttribute((const void*)k_mega,        cudaFuncAttributeMaxDynamicSharedMemorySize, CIF_SMEM);

    k_pre<<<1, 256>>>(nf, nt, cif_b, ln_w);
    k_mega<<<MEGA_BLOCKS, 512, CIF_SMEM>>>(af, cif_w, text_w, text_b);
    k_h1fill<<<MM, 256>>>(af, out);

    // cif_proj (compact): 1-pass fp16
    {
        dim3 grid(DD/128, (MM + 127)/128);
        gemm_h<false><<<grid, 256, SMEM1>>>(1024,
            (const __half*)p_ahi, LDH,
            (const __half*)p_bhi, 1024,
            cif_b, (float*)p_h2, DD);
    }
    k_rms<<<MM, 256>>>(ln_w, out, out_size);

    // text_proj (compact, scatter epilogue): 1-pass fp16
    {
        dim3 grid(DTXT/128, (MM + 127)/128);
        gemm_h<true><<<grid, 256, SMEM1>>>(1024,
            (const __half*)p_ahi, LDH,
            (const __half*)p_bt, DD,
            text_b, out, DTXT);
    }
}